// round 15
// baseline (speedup 1.0000x reference)
#include <cuda_runtime.h>
#include <cuda_bf16.h>
#include <math.h>
#include <stdint.h>

#define NEG_INF (-1e30f)

// Problem constants
#define Bn 8
#define Tn 128
#define Dn 512
#define Hn 512
#define Vn 64
#define Un 32
#define Cn 65          // V + 1
#define CSTRIDE 66     // row stride of tiles; pads (c=65) provably zero
#define TILE_PAD 4352  // g_den per-(b,t) tile floats (>= 65*66=4290)
#define SLOT_PAD 4480  // per-slot floats for product tiles (>= 66*66), 16B mult
#define SLOT_BYTES (SLOT_PAD * 4)   // 17920
#define MROWS (Bn * Tn * Cn)        // 66560 = 520 * 128
#define NB_LOGITS (MROWS / 128)     // 520

// SMEM tile geometry for k_logits (strides in bf16 elements)
#define ASTRIDE 520
#define BSTRIDE 520
#define A_ELEMS (128 * ASTRIDE)
#define B_ELEMS (72 * BSTRIDE)
#define DYN_SMEM ((A_ELEMS + B_ELEMS) * 2)   // 208000 B
#define DSTRIDE 132

#define SCAN_SMEM (4 * SLOT_BYTES)  // 71680 B ring
#define EMIN (-(1 << 28))
#define LN2F 0.69314718055994531f

// product-kernel SMEM strides (bank-conflict-free fragment reads; proven R13)
#define S1 88   // D1s[m][c] : A reads conflict-free
#define S2 76   // D2s[s][k] : B reads conflict-free

// Scratch (__device__ globals; zero-initialized, 16B-aligned)
__device__ __align__(16) float g_proj[Bn * Tn * Hn];
__device__ __align__(16) float g_den[Bn * Tn * TILE_PAD];      // [bt][k*66+c] = exp(logit); pads 0
__device__ __align__(16) float g_pair[Bn * 64 * SLOT_PAD];     // 2-step products
__device__ __align__(16) float g_quad[Bn * 32 * SLOT_PAD];     // 4-step products
__device__ __align__(16) float g_oct [Bn * 16 * SLOT_PAD];     // 8-step products
__device__ __align__(16) __nv_bfloat16 g_WoutT[72 * 512];

// ---------------------------------------------------------------------------
__device__ __forceinline__ float tanh_fast(float x) {
    float y; asm("tanh.approx.f32 %0, %1;" : "=f"(y) : "f"(x)); return y;
}
__device__ __forceinline__ uint32_t smem_u32(const void* p) {
    uint32_t a;
    asm("{ .reg .u64 t; cvta.to.shared.u64 t, %1; cvt.u32.u64 %0, t; }" : "=r"(a) : "l"(p));
    return a;
}
__device__ __forceinline__ void cp_async16(uint32_t saddr, const void* g) {
    asm volatile("cp.async.cg.shared.global [%0], [%1], 16;" :: "r"(saddr), "l"(g));
}
#define CP_COMMIT() asm volatile("cp.async.commit_group;" ::: "memory")
#define CP_WAIT0()  asm volatile("cp.async.wait_group 0;" ::: "memory")
#define CP_WAIT1()  asm volatile("cp.async.wait_group 1;" ::: "memory")

#define MBAR_INIT(addr, cnt) \
    asm volatile("mbarrier.init.shared.b64 [%0], %1;" :: "r"(addr), "r"((uint32_t)(cnt)) : "memory")
#define MBAR_ARRIVE(addr) \
    asm volatile("mbarrier.arrive.shared.b64 _, [%0];" :: "r"(addr) : "memory")

__device__ __forceinline__ void mbar_wait(uint32_t addr, uint32_t phase) {
    asm volatile(
        "{\n\t.reg .pred P;\n\t"
        "LW_%=:\n\t"
        "mbarrier.try_wait.parity.acquire.cta.shared::cta.b64 P, [%0], %1, 0x989680;\n\t"
        "@P bra.uni LD_%=;\n\t"
        "bra.uni LW_%=;\n\t"
        "LD_%=:\n\t}"
        :: "r"(addr), "r"(phase) : "memory");
}

__device__ __forceinline__ void mma16816(float* c, const uint32_t* a, const uint32_t* b) {
    asm volatile(
        "mma.sync.aligned.m16n8k16.row.col.f32.bf16.bf16.f32 "
        "{%0,%1,%2,%3}, {%4,%5,%6,%7}, {%8,%9}, {%0,%1,%2,%3};"
        : "+f"(c[0]), "+f"(c[1]), "+f"(c[2]), "+f"(c[3])
        : "r"(a[0]), "r"(a[1]), "r"(a[2]), "r"(a[3]), "r"(b[0]), "r"(b[1]));
}
__device__ __forceinline__ uint32_t to_tf32(float f) {
    uint32_t u; asm("cvt.rna.tf32.f32 %0, %1;" : "=r"(u) : "f"(f)); return u;
}
__device__ __forceinline__ void mma_tf32(float* c, const uint32_t* a, const uint32_t* b) {
    asm volatile(
        "mma.sync.aligned.m16n8k8.row.col.f32.tf32.tf32.f32 "
        "{%0,%1,%2,%3}, {%4,%5,%6,%7}, {%8,%9}, {%0,%1,%2,%3};"
        : "+f"(c[0]), "+f"(c[1]), "+f"(c[2]), "+f"(c[3])
        : "r"(a[0]), "r"(a[1]), "r"(a[2]), "r"(a[3]), "r"(b[0]), "r"(b[1]));
}

// 2^d for d in [-127, 127], exact, branchless
__device__ __forceinline__ float exp2i(int d) {
    return __int_as_float((d + 127) << 23);
}
// (m,e) <- own*2^eo + oth*2^ep, with own,oth >= 0; m in [1,2) or 0.
__device__ __forceinline__ void accum2(float own, int eo, float oth, int ep,
                                       float& m, int& e) {
    int base = (eo > ep) ? eo : ep;
    int d0 = eo - base; d0 = (d0 < -127) ? -127 : d0;
    int d1 = ep - base; d1 = (d1 < -127) ? -127 : d1;
    float nn = own * exp2i(d0) + oth * exp2i(d1);
    if (nn > 0.f) {
        int bits = __float_as_int(nn);
        e = base + ((bits >> 23) & 0xFF) - 127;
        m = __int_as_float((bits & 0x007FFFFF) | 0x3F800000);
    } else {
        m = 0.f; e = EMIN;
    }
}

// ---------------------------------------------------------------------------
// Kernel 0: transpose + bf16-convert Wout -> g_WoutT[n][k]  (rows n>=65 zero)
// ---------------------------------------------------------------------------
__global__ void k_prep(const float* __restrict__ Wo) {
    const int tid = threadIdx.x + blockIdx.x * blockDim.x;
    for (int e = tid; e < 72 * 512; e += blockDim.x * gridDim.x) {
        int n = e >> 9;
        int k = e & 511;
        float v = (n < Cn) ? Wo[k * Cn + n] : 0.f;
        g_WoutT[e] = __float2bfloat16(v);
    }
}

// ---------------------------------------------------------------------------
// Kernel 1: proj = frames @ W_frame via tf32 mma.sync (m16n8k8).
// ---------------------------------------------------------------------------
#define PAS 36

__global__ __launch_bounds__(128) void k_proj(const float* __restrict__ A,
                                              const float* __restrict__ Bm) {
    __shared__ __align__(16) float As2[2][64 * PAS];
    __shared__ __align__(16) float Bs2[2][32 * PAS];

    const int tid = threadIdx.x;
    const int wid = tid >> 5;
    const int lane = tid & 31;
    const int gq = lane >> 2;
    const int tg = lane & 3;
    const int bm = blockIdx.y * 64;
    const int bn = blockIdx.x * 32;
    const int wm = (wid >> 1) * 32;
    const int wn = (wid & 1) * 16;

    const uint32_t asb[2] = { smem_u32(As2[0]), smem_u32(As2[1]) };
    const uint32_t bsb[2] = { smem_u32(Bs2[0]), smem_u32(Bs2[1]) };

    auto issue = [&](int ch, int buf) {
        const int kc = ch * 32;
#pragma unroll
        for (int l = 0; l < 4; l++) {
            int o = tid + l * 128;
            int row = o >> 3, seg = o & 7;
            cp_async16(asb[buf] + (row * PAS + seg * 4) * 4,
                       A + (size_t)(bm + row) * Dn + kc + seg * 4);
        }
#pragma unroll
        for (int l = 0; l < 2; l++) {
            int o = tid + l * 128;
            int kr = o >> 3, seg = o & 7;
            cp_async16(bsb[buf] + (kr * PAS + seg * 4) * 4,
                       Bm + (size_t)(kc + kr) * Hn + bn + seg * 4);
        }
        CP_COMMIT();
    };

    float acc[2][2][4];
#pragma unroll
    for (int mt = 0; mt < 2; mt++)
#pragma unroll
        for (int nt = 0; nt < 2; nt++)
#pragma unroll
            for (int i = 0; i < 4; i++) acc[mt][nt][i] = 0.f;

    issue(0, 0);

    for (int ch = 0; ch < 16; ch++) {
        const int buf = ch & 1;
        if (ch + 1 < 16) { issue(ch + 1, 1 - buf); CP_WAIT1(); }
        else             { CP_WAIT0(); }
        __syncthreads();

        const float* As = As2[buf];
        const float* Bs = Bs2[buf];
#pragma unroll
        for (int ks = 0; ks < 4; ks++) {
            const int k0 = ks * 8;
            uint32_t bf[2][2];
#pragma unroll
            for (int nt = 0; nt < 2; nt++) {
                int cb = wn + nt * 8 + gq;
                bf[nt][0] = to_tf32(Bs[(k0 + tg) * PAS + cb]);
                bf[nt][1] = to_tf32(Bs[(k0 + tg + 4) * PAS + cb]);
            }
#pragma unroll
            for (int mt = 0; mt < 2; mt++) {
                int rm = wm + mt * 16 + gq;
                uint32_t af[4];
                af[0] = to_tf32(As[rm * PAS + k0 + tg]);
                af[1] = to_tf32(As[(rm + 8) * PAS + k0 + tg]);
                af[2] = to_tf32(As[rm * PAS + k0 + tg + 4]);
                af[3] = to_tf32(As[(rm + 8) * PAS + k0 + tg + 4]);
#pragma unroll
                for (int nt = 0; nt < 2; nt++) mma_tf32(acc[mt][nt], af, bf[nt]);
            }
        }
        __syncthreads();
    }

#pragma unroll
    for (int mt = 0; mt < 2; mt++) {
        int row = bm + wm + mt * 16 + gq;
#pragma unroll
        for (int nt = 0; nt < 2; nt++) {
            int col = bn + wn + nt * 8 + tg * 2;
            *reinterpret_cast<float2*>(&g_proj[(size_t)row * Hn + col]) =
                make_float2(acc[mt][nt][0], acc[mt][nt][1]);
            *reinterpret_cast<float2*>(&g_proj[(size_t)(row + 8) * Hn + col]) =
                make_float2(acc[mt][nt][2], acc[mt][nt][3]);
        }
    }
}

// ---------------------------------------------------------------------------
// Kernel 2: logits via mma.sync bf16 (m16n8k16), 256 threads (8 warps).
// Stores EXP of all logits transposed into g_den[bt][k*66 + c].
// ---------------------------------------------------------------------------
__global__ __launch_bounds__(256) void k_logits(const float* __restrict__ ce) {
    extern __shared__ __align__(16) __nv_bfloat16 dynsmem[];
    __nv_bfloat16* Asm = dynsmem;
    __nv_bfloat16* Bsm = dynsmem + A_ELEMS;
    __shared__ __align__(16) float p[3 * 512];
    __shared__ int btc[128];

    const int tid = threadIdx.x;
    const int wid = tid >> 5;
    const int lane = tid & 31;
    const int gq = lane >> 2;
    const int tg = lane & 3;
    const int g0 = blockIdx.x * 128;
    const int bt0 = g0 / 65;

    for (int i = tid; i < 3 * 512; i += 256) {
        int bt = bt0 + (i >> 9);
        p[i] = (bt < Bn * Tn) ? g_proj[(size_t)bt * Hn + (i & 511)] : 0.f;
    }
    for (int e = tid; e < 72 * 64; e += 256) {
        int n = e >> 6, kq = e & 63;
        *reinterpret_cast<uint4*>(&Bsm[n * BSTRIDE + kq * 8]) =
            *reinterpret_cast<const uint4*>(&g_WoutT[n * 512 + kq * 8]);
    }
    if (tid < 128) {
        int bt = (g0 + tid) / 65;
        btc[tid] = bt * TILE_PAD + (g0 + tid - bt * 65);
    }
    __syncthreads();

    {
        const int half = tid >> 7;
        const int col = (tid & 127) * 4;
        int g = g0 + half * 64;
        int bt = g / 65;
        int c = g - bt * 65;
#pragma unroll 4
        for (int rr = 0; rr < 64; rr++) {
            int r = half * 64 + rr;
            int pb = bt - bt0;
            float4 pe = *reinterpret_cast<const float4*>(&p[pb * 512 + col]);
            float4 cv = *reinterpret_cast<const float4*>(&ce[(size_t)c * Hn + col]);
            __nv_bfloat162 b0 = __floats2bfloat162_rn(tanh_fast(pe.x + cv.x),
                                                      tanh_fast(pe.y + cv.y));
            __nv_bfloat162 b1 = __floats2bfloat162_rn(tanh_fast(pe.z + cv.z),
                                                      tanh_fast(pe.w + cv.w));
            uint2 pk = make_uint2(*reinterpret_cast<uint32_t*>(&b0),
                                  *reinterpret_cast<uint32_t*>(&b1));
            *reinterpret_cast<uint2*>(&Asm[r * ASTRIDE + col]) = pk;
            if (++c == 65) { c = 0; ++bt; }
        }
    }
    __syncthreads();

    float acc[9][4];
#pragma unroll
    for (int nt = 0; nt < 9; nt++)
#pragma unroll
        for (int i = 0; i < 4; i++) acc[nt][i] = 0.f;

    const int wbase = wid * 16;
#pragma unroll 2
    for (int kk = 0; kk < 32; kk++) {
        const int k0 = kk * 16;
        uint32_t bf[9][2];
#pragma unroll
        for (int nt = 0; nt < 9; nt++) {
            int n = nt * 8 + gq;
            bf[nt][0] = *reinterpret_cast<const uint32_t*>(&Bsm[n * BSTRIDE + k0 + tg * 2]);
            bf[nt][1] = *reinterpret_cast<const uint32_t*>(&Bsm[n * BSTRIDE + k0 + 8 + tg * 2]);
        }
        const int r0 = wbase + gq;
        uint32_t af[4];
        af[0] = *reinterpret_cast<const uint32_t*>(&Asm[r0 * ASTRIDE + k0 + tg * 2]);
        af[1] = *reinterpret_cast<const uint32_t*>(&Asm[(r0 + 8) * ASTRIDE + k0 + tg * 2]);
        af[2] = *reinterpret_cast<const uint32_t*>(&Asm[r0 * ASTRIDE + k0 + 8 + tg * 2]);
        af[3] = *reinterpret_cast<const uint32_t*>(&Asm[(r0 + 8) * ASTRIDE + k0 + 8 + tg * 2]);
#pragma unroll
        for (int nt = 0; nt < 9; nt++) mma16816(acc[nt], af, bf[nt]);
    }
    __syncthreads();

    float* d_sm = reinterpret_cast<float*>(dynsmem);
    {
        const int r0 = wbase + gq;
#pragma unroll
        for (int nt = 0; nt < 9; nt++) {
            const int col = nt * 8 + tg * 2;
            d_sm[col * DSTRIDE + r0]           = acc[nt][0];
            d_sm[(col + 1) * DSTRIDE + r0]     = acc[nt][1];
            d_sm[col * DSTRIDE + r0 + 8]       = acc[nt][2];
            d_sm[(col + 1) * DSTRIDE + r0 + 8] = acc[nt][3];
        }
    }
    __syncthreads();

    for (int e = tid; e < Cn * 128; e += 256) {
        int k = e >> 7;
        int r = e & 127;
        g_den[(size_t)btc[r] + k * CSTRIDE] = __expf(d_sm[k * DSTRIDE + r]);
    }
}

// ---------------------------------------------------------------------------
// Kernel 2.5a: pairwise transition products via tf32 mma.sync (PROVEN R13).
// Dense M[c][s]: s>=1: T[s*66+c] + (c==s)*bl[s]; s=0: (c==0)*bl[0].
// Ptile[s*66+c] = (M_{2j} * M_{2j+1})[c][s]. Odd tail: dense M_{2j}.
// ---------------------------------------------------------------------------
__global__ __launch_bounds__(160) void k_pair(const int* __restrict__ nf) {
    __shared__ float D1s[72 * S1];
    __shared__ float D2s[72 * S2];

    const int tid = threadIdx.x;
    const int wid = tid >> 5;
    const int lane = tid & 31;
    const int gq = lane >> 2;
    const int tg = lane & 3;
    const int j = blockIdx.x;
    const int b = blockIdx.y;
    const int Tb = nf[b];
    const int t0 = 2 * j;
    if (t0 >= Tb) return;
    const bool single = (t0 + 1 >= Tb);

    const float* T1 = g_den + (size_t)(b * Tn + t0) * TILE_PAD;
    const float* T2 = single ? T1 : T1 + TILE_PAD;

    for (int i = tid; i < 72 * S1; i += 160) D1s[i] = 0.f;
    for (int i = tid; i < 72 * S2; i += 160) D2s[i] = 0.f;
    __syncthreads();

    for (int i = tid; i < 65 * 66; i += 160) {
        int r = i / 66, c = i - r * 66;
        D1s[r * S1 + c] = T1[i];
        D2s[r * S2 + c] = T2[i];
    }
    __syncthreads();

    if (tid < 65) {
        float b1 = T1[tid];
        float b2 = T2[tid];
        if (tid >= 1) {
            D1s[tid * S1 + tid] += b1;
            D2s[tid * S2 + tid] += b2;
        }
        D1s[tid] = (tid == 0) ? b1 : 0.f;
        D2s[tid] = (tid == 0) ? b2 : 0.f;
    }
    __syncthreads();

    float* outp = g_pair + (size_t)(b * 64 + j) * SLOT_PAD;

    if (single) {
        for (int i = tid; i < 65 * 66; i += 160) {
            int s = i / 66, c = i - s * 66;
            outp[i] = D1s[s * S1 + c];
        }
        return;
    }

    const int row0 = wid * 16 + gq;
    float acc[9][4];
#pragma unroll
    for (int nt = 0; nt < 9; nt++)
#pragma unroll
        for (int i = 0; i < 4; i++) acc[nt][i] = 0.f;

#pragma unroll
    for (int ks = 0; ks < 9; ks++) {
        const int k0 = ks * 8;
        uint32_t af[4];
        af[0] = to_tf32(D1s[(k0 + tg) * S1 + row0]);
        af[1] = to_tf32(D1s[(k0 + tg) * S1 + row0 + 8]);
        af[2] = to_tf32(D1s[(k0 + tg + 4) * S1 + row0]);
        af[3] = to_tf32(D1s[(k0 + tg + 4) * S1 + row0 + 8]);
        uint32_t bf[9][2];
#pragma unroll
        for (int nt = 0; nt < 9; nt++) {
            int sc = nt * 8 + gq;
            bf[nt][0] = to_tf32(D2s[sc * S2 + k0 + tg]);
            bf[nt][1] = to_tf32(D2s[sc * S2 + k0 + tg + 4]);
        }
#pragma unroll
        for (int nt = 0; nt < 9; nt++) mma_tf32(acc[nt], af, bf[nt]);
    }

#pragma unroll
    for (int nt = 0; nt < 9; nt++) {
        const int s0 = nt * 8 + tg * 2;
        if (row0 < 65) {
            if (s0 < 65)     outp[s0 * 66 + row0]       = acc[nt][0];
            if (s0 + 1 < 65) outp[(s0 + 1) * 66 + row0] = acc[nt][1];
        }
        if (row0 + 8 < 65) {
            if (s0 < 65)     outp[s0 * 66 + row0 + 8]       = acc[nt][2];
            if (s0 + 1 < 65) outp[(s0 + 1) * 66 + row0 + 8] = acc[nt][3];
        }
    }
}

// ---------------------------------------------------------------------------
// Kernel 2.5b: generic product level. lvl=1: g_pair->g_quad (32 slots),
// lvl=2: g_quad->g_oct (16 slots). Tiles already dense: staging is two
// STRAIGHT float2 strided copies, no densify, no transpose.
//   D1s[m*S1+c] = A[m*66+c]   (A = earlier tile, Pa[c][m])
//   D2s[s*S2+m] = B[s*66+m]   (B = later tile,   Pb[m][s])
//   C[c][s] = sum_m Pa[c][m]*Pb[m][s] -> out[s*66+c]
// ---------------------------------------------------------------------------
__global__ __launch_bounds__(160) void k_mul(const int* __restrict__ nf, int lvl) {
    __shared__ float D1s[72 * S1];
    __shared__ float D2s[72 * S2];

    const int tid = threadIdx.x;
    const int wid = tid >> 5;
    const int lane = tid & 31;
    const int gq = lane >> 2;
    const int tg = lane & 3;
    const int j = blockIdx.x;
    const int b = blockIdx.y;
    const int Tb = nf[b];
    const int n_src = (Tb + (1 << lvl) - 1) >> lvl;
    if (2 * j >= n_src) return;
    const bool single = (2 * j + 1 >= n_src);

    const int smax = (lvl == 1) ? 64 : 32;
    const float* srcb = (lvl == 1) ? g_pair : g_quad;
    float* dstb = (lvl == 1) ? g_quad : g_oct;
    const float* A = srcb + (size_t)(b * smax + 2 * j) * SLOT_PAD;
    const float* Bt = A + SLOT_PAD;
    float* outp = dstb + (size_t)(b * (smax >> 1) + j) * SLOT_PAD;

    if (single) {
        for (int i = tid; i < 65 * 66; i += 160) outp[i] = A[i];
        return;
    }

    // zero only load-bearing pads: D1s k-rows 65..71 (A), D2s k-cols 66..71 (B)
    for (int i = tid; i < 7 * S1; i += 160) D1s[65 * S1 + i] = 0.f;
    for (int i = tid; i < 65 * 6; i += 160) {
        int r = i / 6;
        D2s[r * S2 + 66 + (i - r * 6)] = 0.f;
    }
    // straight strided copies (float2); src col 65 is pad zero -> covers m=65
    for (int i = tid; i < 65 * 33; i += 160) {
        int r = i / 33, c2 = (i - r * 33) * 2;
        *reinterpret_cast<float2*>(&D1s[r * S1 + c2]) =
            *reinterpret_cast<const float2*>(&A[r * 66 + c2]);
        *reinterpret_cast<float2*>(&D2s[r * S2 + c2]) =
            *reinterpret_cast<const float2*>(&Bt[r * 66 + c2]);
    }
    __syncthreads();

    const int row0 = wid * 16 + gq;
    float acc[9][4];
#pragma unroll
    for (int nt = 0; nt < 9; nt++)
#pragma unroll
        for (int i = 0; i < 4; i++) acc[nt][i] = 0.f;

#pragma unroll
    for (int ks = 0; ks < 9; ks++) {
        const int k0 = ks * 8;
        uint32_t af[4];
        af[0] = to_tf32(D1s[(k0 + tg) * S1 + row0]);
        af[1] = to_tf32(D1s[(k0 + tg) * S1 + row0 + 8]);
        af[2] = to_tf32(D1s[(k0 + tg + 4) * S1 + row0]);
        af[3] = to_tf32(D1s[(k0 + tg + 4) * S1 + row0 + 8]);
        uint32_t bf[9][2];
#pragma unroll
        for (int nt = 0; nt < 9; nt++) {
            int sc = nt * 8 + gq;
            bf[nt][0] = to_tf32(D2s[sc * S2 + k0 + tg]);
            bf[nt][1] = to_tf32(D2s[sc * S2 + k0 + tg + 4]);
        }
#pragma unroll
        for (int nt = 0; nt < 9; nt++) mma_tf32(acc[nt], af, bf[nt]);
    }

#pragma unroll
    for (int nt = 0; nt < 9; nt++) {
        const int s0 = nt * 8 + tg * 2;
        if (row0 < 65) {
            if (s0 < 65)     outp[s0 * 66 + row0]       = acc[nt][0];
            if (s0 + 1 < 65) outp[(s0 + 1) * 66 + row0] = acc[nt][1];
        }
        if (row0 + 8 < 65) {
            if (s0 < 65)     outp[s0 * 66 + row0 + 8]       = acc[nt][2];
            if (s0 + 1 < 65) outp[(s0 + 1) * 66 + row0 + 8] = acc[nt][3];
        }
    }
}

// ---------------------------------------------------------------------------
// Kernel 3: warp-specialized scan over OCT tiles (<=16 steps). 224 threads.
//  warps 0-1 : denominator (lane -> state; w1 lane31 also state 64);
//              renorm EVERY step (power-of-2, shuffle + bar).
//  warp 2    : numerator over ORIGINAL g_den (static 4-deep register ring).
//  warps 3-6 : producers of g_oct tiles (slot = wid-3), empty count = 2.
// ---------------------------------------------------------------------------
__global__ __launch_bounds__(224) void k_scan(const int* __restrict__ num_frames,
                                              const int* __restrict__ labels,
                                              const int* __restrict__ num_labels,
                                              float* __restrict__ out) {
    extern __shared__ __align__(16) float tilebuf[];   // 4 * SLOT_PAD floats
    __shared__ __align__(16) float beta_sh[2][68];
    __shared__ float maxw[2];
    __shared__ float nm_fin[Un + 1];
    __shared__ int ne_fin[Un + 1];
    __shared__ int esum_sh;
    __shared__ __align__(8) unsigned long long mbars[8];   // full[0..3], empty[4..7]

    const int b = blockIdx.x;
    const int tid = threadIdx.x;
    const int wid = tid >> 5;
    const int lane = tid & 31;
    const int Tb = num_frames[b];          // in [64, 128]
    const int To = (Tb + 7) >> 3;          // oct steps, in [8, 16]

    uint32_t mb_full[4], mb_empty[4];
#pragma unroll
    for (int s = 0; s < 4; s++) {
        mb_full[s] = smem_u32(&mbars[s]);
        mb_empty[s] = smem_u32(&mbars[4 + s]);
    }
    if (tid == 0) {
#pragma unroll
        for (int s = 0; s < 4; s++) {
            MBAR_INIT(mb_full[s], 32);
            MBAR_INIT(mb_empty[s], 2);
        }
    }
    if (tid < 68) {
        beta_sh[0][tid] = (tid == 0) ? 1.f : 0.f;
        beta_sh[1][tid] = 0.f;
    }
    __syncthreads();

    const float* pbase = g_oct + (size_t)(b * 16) * SLOT_PAD;

    if (wid >= 3) {
        const int p = wid - 3;
        const uint32_t dst0 = smem_u32(tilebuf) + p * SLOT_BYTES;
        int eph = 1;
        for (int pp = p; pp < To; pp += 4) {
            mbar_wait(mb_empty[p], (uint32_t)eph);
            eph ^= 1;
            const float* src = pbase + (size_t)pp * SLOT_PAD;
#pragma unroll
            for (int i = lane; i < SLOT_PAD / 4; i += 32)
                cp_async16(dst0 + i * 16, src + i * 4);
            CP_COMMIT();
            CP_WAIT0();
            MBAR_ARRIVE(mb_full[p]);
        }
    } else if (wid < 2) {
        const int st = wid * 32 + lane;
        const bool ex = (wid == 1 && lane == 31);
        const int rowoff = st * CSTRIDE;
        float nv64 = 0.f;
        int esum = 0;

        for (int pp = 0; pp < To; pp++) {
            const int s = pp & 3;
            mbar_wait(mb_full[s], (uint32_t)((pp >> 2) & 1));
            const float* Tt = tilebuf + s * SLOT_PAD;
            const float* bsh = beta_sh[pp & 1];
            const float2* b2 = reinterpret_cast<const float2*>(bsh);

            const float2* r2 = reinterpret_cast<const float2*>(Tt + rowoff);
            float s0 = 0.f, s1 = 0.f, s2 = 0.f, s3 = 0.f;
#pragma unroll 8
            for (int c2 = 0; c2 < 32; c2 += 2) {
                float2 a0 = r2[c2],     w0v = b2[c2];
                float2 a1 = r2[c2 + 1], w1v = b2[c2 + 1];
                s0 += a0.x * w0v.x; s1 += a0.y * w0v.y;
                s2 += a1.x * w1v.x; s3 += a1.y * w1v.y;
            }
            {
                float2 a32 = r2[32], w32 = b2[32];
                s0 += a32.x * w32.x; s1 += a32.y * w32.y;
            }
            float nv = (s0 + s1) + (s2 + s3);

            if (ex) {
                const float2* r64 = reinterpret_cast<const float2*>(Tt + 64 * CSTRIDE);
                float t0 = 0.f, t1 = 0.f;
#pragma unroll 8
                for (int c2 = 0; c2 < 32; c2++) {
                    float2 a0 = r64[c2], w0v = b2[c2];
                    t0 += a0.x * w0v.x; t1 += a0.y * w0v.y;
                }
                float2 a32 = r64[32], w32 = b2[32];
                nv64 = t0 + t1 + a32.x * w32.x + a32.y * w32.y;
            }

            __syncwarp();
            if (lane == 0) MBAR_ARRIVE(mb_empty[s]);

            // renorm every oct step
            {
                float mx = ex ? fmaxf(nv, nv64) : nv;
#pragma unroll
                for (int o = 16; o; o >>= 1)
                    mx = fmaxf(mx, __shfl_xor_sync(0xffffffffu, mx, o));
                if (lane == 0) maxw[wid] = mx;
                asm volatile("bar.sync 1, 64;" ::: "memory");
                float gm = fmaxf(maxw[0], maxw[1]);
                int eb = ((__float_as_int(gm) >> 23) & 0xFF) - 127;
                float sc = exp2i(-eb);
                nv *= sc; nv64 *= sc; esum += eb;
            }

            beta_sh[1 - (pp & 1)][st] = nv;
            if (ex) beta_sh[1 - (pp & 1)][64] = nv64;
            asm volatile("bar.sync 1, 64;" ::: "memory");
        }
        if (tid == 0) esum_sh = esum;
    } else {
        // numerator (warp 2): static-indexed 4-deep register ring over g_den
        const float* base = g_den + (size_t)(b * Tn) * TILE_PAD;
        const int* lb = labels + b * Un;
        const int j = lane;
        const int cj = (j == 0) ? 0 : lb[j - 1];
        const int cm = (j >= 2) ? lb[j - 2] : 0;
        const int c32 = lb[31], c31 = lb[30];
        const bool l0 = (j == 0);
        float m = l0 ? 1.f : 0.f;
        int e = l0 ? 0 : EMIN;
        float m2 = 0.f;
        int e2 = EMIN;

        const float* gA = base + cj;
        const float* gB = base + cj * CSTRIDE + cm;
        const float* gC = base + c32;
        const float* gD = base + c32 * CSTRIDE + c31;

        float va[4], vb[4], vc[4], vd[4];
#pragma unroll
        for (int k = 0; k < 4; k++) {
            size_t o = (size_t)k * TILE_PAD;
            va[k] = gA[o];
            vb[k] = (j > 0) ? gB[o] : 0.f;
            vc[k] = l0 ? gC[o] : 0.f;
            vd[k] = l0 ? gD[o] : 0.f;
        }

        for (int tb = 0; tb < Tb; tb += 4) {
            float na[4], nb[4], nc[4], nd[4];
#pragma unroll
            for (int k = 0; k < 4; k++) {
                int tt = tb + 4 + k;
                if (tt > Tb - 1) tt = Tb - 1;
                size_t o = (size_t)tt * TILE_PAD;
                na[k] = gA[o];
                nb[k] = (j > 0) ? gB[o] : 0.f;
                nc[k] = l0 ? gC[o] : 0.f;
                nd[k] = l0 ? gD[o] : 0.f;
            }
#pragma unroll
            for (int k = 0; k < 4; k++) {
                if (tb + k < Tb) {
                    float mp = __shfl_up_sync(0xffffffffu, m, 1);
                    int epv = __shfl_up_sync(0xffffffffu, e, 1);
                    float m31 = __shfl_sync(0xffffffffu, m, 31);
                    int e31 = __shfl_sync(0xffffffffu, e, 31);

                    float own = m * va[k];
                    float oth = (j > 0) ? mp * vb[k] : 0.f;
                    int epo = (j > 0) ? epv : EMIN;
                    accum2(own, e, oth, epo, m, e);

                    if (l0) {
                        float own2 = m2 * vc[k];
                        float oth2 = m31 * vd[k];
                        accum2(own2, e2, oth2, e31, m2, e2);
                    }
                }
            }
#pragma unroll
            for (int k = 0; k < 4; k++) { va[k] = na[k]; vb[k] = nb[k]; vc[k] = nc[k]; vd[k] = nd[k]; }
        }
        nm_fin[j] = m;
        ne_fin[j] = e;
        if (l0) { nm_fin[32] = m2; ne_fin[32] = e2; }
    }

    __syncthreads();
    if (tid == 0) {
        const float* bf = beta_sh[To & 1];
        float ssum = 0.f;
        for (int c = 0; c < Cn; c++) ssum += bf[c];
        float den = (float)esum_sh * LN2F + __logf(ssum);
        int nl = num_labels[b];
        float num = __logf(nm_fin[nl]) + (float)ne_fin[nl] * LN2F;
        out[b] = den - num;
    }
}

// ---------------------------------------------------------------------------
extern "C" void kernel_launch(void* const* d_in, const int* in_sizes, int n_in,
                              void* d_out, int out_size) {
    const float* frames = (const float*)d_in[0];   // (8,128,512)
    const float* Wf     = (const float*)d_in[1];   // (512,512)
    const float* ce     = (const float*)d_in[2];   // (65,512)
    const float* Wo     = (const float*)d_in[3];   // (512,65)
    const int* nf       = (const int*)d_in[4];     // (8,)
    const int* labels   = (const int*)d_in[5];     // (8,32)
    const int* nl       = (const int*)d_in[6];     // (8,)
    float* out = (float*)d_out;                    // (8,)

    cudaFuncSetAttribute(k_logits, cudaFuncAttributeMaxDynamicSharedMemorySize, DYN_SMEM);
    cudaFuncSetAttribute(k_scan, cudaFuncAttributeMaxDynamicSharedMemorySize, SCAN_SMEM);

    k_prep<<<4, 256>>>(Wo);
    k_proj<<<dim3(Hn / 32, (Bn * Tn) / 64), 128>>>(frames, Wf);
    k_logits<<<NB_LOGITS, 256, DYN_SMEM>>>(ce);
    k_pair<<<dim3(64, Bn), 160>>>(nf);
    k_mul<<<dim3(32, Bn), 160>>>(nf, 1);
    k_mul<<<dim3(16, Bn), 160>>>(nf, 2);
    k_scan<<<Bn, 224, SCAN_SMEM>>>(nf, labels, nl, out);
}

// round 16
// speedup vs baseline: 1.1164x; 1.1164x over previous
#include <cuda_runtime.h>
#include <cuda_bf16.h>
#include <math.h>
#include <stdint.h>

#define NEG_INF (-1e30f)

// Problem constants
#define Bn 8
#define Tn 128
#define Dn 512
#define Hn 512
#define Vn 64
#define Un 32
#define Cn 65          // V + 1
#define CSTRIDE 66     // row stride of tiles; pads (c=65) provably zero
#define TILE_PAD 4352  // g_den per-(b,t) tile floats (>= 65*66=4290)
#define SLOT_PAD 4480  // per-slot floats for product tiles (>= 66*66), 16B mult
#define SLOT_BYTES (SLOT_PAD * 4)   // 17920
#define MROWS (Bn * Tn * Cn)        // 66560 = 520 * 128
#define NB_LOGITS (MROWS / 128)     // 520

// k_logits chunked tile geometry (bf16 elems)
#define AST 136                     // chunk row stride (128 data + 8 pad)
#define A_CH (128 * AST)            // 17408 elems = 34816 B
#define B_CH (72 * AST)             //  9792 elems = 19584 B
#define DYN_SMEM ((A_CH + B_CH) * 2)   // 54400 B -> 3 blocks/SM
#define DSTRIDE 132

#define SCAN_SMEM (4 * SLOT_BYTES)  // 71680 B ring
#define EMIN (-(1 << 28))
#define LN2F 0.69314718055994531f

// product-kernel SMEM strides (bank-conflict-free fragment reads; proven R13)
#define S1 88   // D1s[m][c] : A reads conflict-free
#define S2 76   // D2s[s][k] : B reads conflict-free

// Scratch (__device__ globals; zero-initialized, 16B-aligned)
__device__ __align__(16) float g_proj[Bn * Tn * Hn];
__device__ __align__(16) float g_den[Bn * Tn * TILE_PAD];      // [bt][k*66+c] = exp(logit); pads 0
__device__ __align__(16) float g_pair[Bn * 64 * SLOT_PAD];     // 2-step products
__device__ __align__(16) float g_quad[Bn * 32 * SLOT_PAD];     // 4-step products
__device__ __align__(16) float g_oct [Bn * 16 * SLOT_PAD];     // 8-step products
__device__ __align__(16) __nv_bfloat16 g_WoutT[72 * 512];

// ---------------------------------------------------------------------------
__device__ __forceinline__ float tanh_fast(float x) {
    float y; asm("tanh.approx.f32 %0, %1;" : "=f"(y) : "f"(x)); return y;
}
__device__ __forceinline__ uint32_t smem_u32(const void* p) {
    uint32_t a;
    asm("{ .reg .u64 t; cvta.to.shared.u64 t, %1; cvt.u32.u64 %0, t; }" : "=r"(a) : "l"(p));
    return a;
}
__device__ __forceinline__ void cp_async16(uint32_t saddr, const void* g) {
    asm volatile("cp.async.cg.shared.global [%0], [%1], 16;" :: "r"(saddr), "l"(g));
}
#define CP_COMMIT() asm volatile("cp.async.commit_group;" ::: "memory")
#define CP_WAIT0()  asm volatile("cp.async.wait_group 0;" ::: "memory")
#define CP_WAIT1()  asm volatile("cp.async.wait_group 1;" ::: "memory")

#define MBAR_INIT(addr, cnt) \
    asm volatile("mbarrier.init.shared.b64 [%0], %1;" :: "r"(addr), "r"((uint32_t)(cnt)) : "memory")
#define MBAR_ARRIVE(addr) \
    asm volatile("mbarrier.arrive.shared.b64 _, [%0];" :: "r"(addr) : "memory")

__device__ __forceinline__ void mbar_wait(uint32_t addr, uint32_t phase) {
    asm volatile(
        "{\n\t.reg .pred P;\n\t"
        "LW_%=:\n\t"
        "mbarrier.try_wait.parity.acquire.cta.shared::cta.b64 P, [%0], %1, 0x989680;\n\t"
        "@P bra.uni LD_%=;\n\t"
        "bra.uni LW_%=;\n\t"
        "LD_%=:\n\t}"
        :: "r"(addr), "r"(phase) : "memory");
}

__device__ __forceinline__ void mma16816(float* c, const uint32_t* a, const uint32_t* b) {
    asm volatile(
        "mma.sync.aligned.m16n8k16.row.col.f32.bf16.bf16.f32 "
        "{%0,%1,%2,%3}, {%4,%5,%6,%7}, {%8,%9}, {%0,%1,%2,%3};"
        : "+f"(c[0]), "+f"(c[1]), "+f"(c[2]), "+f"(c[3])
        : "r"(a[0]), "r"(a[1]), "r"(a[2]), "r"(a[3]), "r"(b[0]), "r"(b[1]));
}
__device__ __forceinline__ uint32_t to_tf32(float f) {
    uint32_t u; asm("cvt.rna.tf32.f32 %0, %1;" : "=r"(u) : "f"(f)); return u;
}
__device__ __forceinline__ void mma_tf32(float* c, const uint32_t* a, const uint32_t* b) {
    asm volatile(
        "mma.sync.aligned.m16n8k8.row.col.f32.tf32.tf32.f32 "
        "{%0,%1,%2,%3}, {%4,%5,%6,%7}, {%8,%9}, {%0,%1,%2,%3};"
        : "+f"(c[0]), "+f"(c[1]), "+f"(c[2]), "+f"(c[3])
        : "r"(a[0]), "r"(a[1]), "r"(a[2]), "r"(a[3]), "r"(b[0]), "r"(b[1]));
}

// 2^d for d in [-127, 127], exact, branchless
__device__ __forceinline__ float exp2i(int d) {
    return __int_as_float((d + 127) << 23);
}
// (m,e) <- own*2^eo + oth*2^ep, with own,oth >= 0; m in [1,2) or 0.
__device__ __forceinline__ void accum2(float own, int eo, float oth, int ep,
                                       float& m, int& e) {
    int base = (eo > ep) ? eo : ep;
    int d0 = eo - base; d0 = (d0 < -127) ? -127 : d0;
    int d1 = ep - base; d1 = (d1 < -127) ? -127 : d1;
    float nn = own * exp2i(d0) + oth * exp2i(d1);
    if (nn > 0.f) {
        int bits = __float_as_int(nn);
        e = base + ((bits >> 23) & 0xFF) - 127;
        m = __int_as_float((bits & 0x007FFFFF) | 0x3F800000);
    } else {
        m = 0.f; e = EMIN;
    }
}

// ---------------------------------------------------------------------------
// Kernel 0: transpose + bf16-convert Wout -> g_WoutT[n][k]  (rows n>=65 zero)
// ---------------------------------------------------------------------------
__global__ void k_prep(const float* __restrict__ Wo) {
    const int tid = threadIdx.x + blockIdx.x * blockDim.x;
    for (int e = tid; e < 72 * 512; e += blockDim.x * gridDim.x) {
        int n = e >> 9;
        int k = e & 511;
        float v = (n < Cn) ? Wo[k * Cn + n] : 0.f;
        g_WoutT[e] = __float2bfloat16(v);
    }
}

// ---------------------------------------------------------------------------
// Kernel 1: proj = frames @ W_frame via tf32 mma.sync (m16n8k8).
// ---------------------------------------------------------------------------
#define PAS 36

__global__ __launch_bounds__(128) void k_proj(const float* __restrict__ A,
                                              const float* __restrict__ Bm) {
    __shared__ __align__(16) float As2[2][64 * PAS];
    __shared__ __align__(16) float Bs2[2][32 * PAS];

    const int tid = threadIdx.x;
    const int wid = tid >> 5;
    const int lane = tid & 31;
    const int gq = lane >> 2;
    const int tg = lane & 3;
    const int bm = blockIdx.y * 64;
    const int bn = blockIdx.x * 32;
    const int wm = (wid >> 1) * 32;
    const int wn = (wid & 1) * 16;

    const uint32_t asb[2] = { smem_u32(As2[0]), smem_u32(As2[1]) };
    const uint32_t bsb[2] = { smem_u32(Bs2[0]), smem_u32(Bs2[1]) };

    auto issue = [&](int ch, int buf) {
        const int kc = ch * 32;
#pragma unroll
        for (int l = 0; l < 4; l++) {
            int o = tid + l * 128;
            int row = o >> 3, seg = o & 7;
            cp_async16(asb[buf] + (row * PAS + seg * 4) * 4,
                       A + (size_t)(bm + row) * Dn + kc + seg * 4);
        }
#pragma unroll
        for (int l = 0; l < 2; l++) {
            int o = tid + l * 128;
            int kr = o >> 3, seg = o & 7;
            cp_async16(bsb[buf] + (kr * PAS + seg * 4) * 4,
                       Bm + (size_t)(kc + kr) * Hn + bn + seg * 4);
        }
        CP_COMMIT();
    };

    float acc[2][2][4];
#pragma unroll
    for (int mt = 0; mt < 2; mt++)
#pragma unroll
        for (int nt = 0; nt < 2; nt++)
#pragma unroll
            for (int i = 0; i < 4; i++) acc[mt][nt][i] = 0.f;

    issue(0, 0);

    for (int ch = 0; ch < 16; ch++) {
        const int buf = ch & 1;
        if (ch + 1 < 16) { issue(ch + 1, 1 - buf); CP_WAIT1(); }
        else             { CP_WAIT0(); }
        __syncthreads();

        const float* As = As2[buf];
        const float* Bs = Bs2[buf];
#pragma unroll
        for (int ks = 0; ks < 4; ks++) {
            const int k0 = ks * 8;
            uint32_t bf[2][2];
#pragma unroll
            for (int nt = 0; nt < 2; nt++) {
                int cb = wn + nt * 8 + gq;
                bf[nt][0] = to_tf32(Bs[(k0 + tg) * PAS + cb]);
                bf[nt][1] = to_tf32(Bs[(k0 + tg + 4) * PAS + cb]);
            }
#pragma unroll
            for (int mt = 0; mt < 2; mt++) {
                int rm = wm + mt * 16 + gq;
                uint32_t af[4];
                af[0] = to_tf32(As[rm * PAS + k0 + tg]);
                af[1] = to_tf32(As[(rm + 8) * PAS + k0 + tg]);
                af[2] = to_tf32(As[rm * PAS + k0 + tg + 4]);
                af[3] = to_tf32(As[(rm + 8) * PAS + k0 + tg + 4]);
#pragma unroll
                for (int nt = 0; nt < 2; nt++) mma_tf32(acc[mt][nt], af, bf[nt]);
            }
        }
        __syncthreads();
    }

#pragma unroll
    for (int mt = 0; mt < 2; mt++) {
        int row = bm + wm + mt * 16 + gq;
#pragma unroll
        for (int nt = 0; nt < 2; nt++) {
            int col = bn + wn + nt * 8 + tg * 2;
            *reinterpret_cast<float2*>(&g_proj[(size_t)row * Hn + col]) =
                make_float2(acc[mt][nt][0], acc[mt][nt][1]);
            *reinterpret_cast<float2*>(&g_proj[(size_t)(row + 8) * Hn + col]) =
                make_float2(acc[mt][nt][2], acc[mt][nt][3]);
        }
    }
}

// ---------------------------------------------------------------------------
// Kernel 2: logits via mma.sync bf16 (m16n8k16), 256 threads (8 warps).
// K-CHUNKED (4 chunks of 128): small SMEM (54.4 KB) -> 3 blocks/SM, so the
// tanh fill phase of one block overlaps the HMMA phase of another.
// Stores EXP of all logits transposed into g_den[bt][k*66 + c].
// ---------------------------------------------------------------------------
__global__ __launch_bounds__(256) void k_logits(const float* __restrict__ ce) {
    extern __shared__ __align__(16) __nv_bfloat16 dynsmem[];
    __nv_bfloat16* Asm = dynsmem;             // [128][AST]
    __nv_bfloat16* Bsm = dynsmem + A_CH;      // [72][AST]
    __shared__ __align__(16) float p[3 * 512];
    __shared__ int btc[128];                  // output base offsets
    __shared__ short rc_c[128], rc_pb[128];   // row -> (c, proj-slot)

    const int tid = threadIdx.x;
    const int wid = tid >> 5;
    const int lane = tid & 31;
    const int gq = lane >> 2;
    const int tg = lane & 3;
    const int g0 = blockIdx.x * 128;
    const int bt0 = g0 / 65;

    for (int i = tid; i < 3 * 512; i += 256) {
        int bt = bt0 + (i >> 9);
        p[i] = (bt < Bn * Tn) ? g_proj[(size_t)bt * Hn + (i & 511)] : 0.f;
    }
    if (tid < 128) {
        int bt = (g0 + tid) / 65;
        int c = g0 + tid - bt * 65;
        btc[tid] = bt * TILE_PAD + c;
        rc_c[tid] = (short)c;
        rc_pb[tid] = (short)(bt - bt0);
    }
    __syncthreads();

    float acc[9][4];
#pragma unroll
    for (int nt = 0; nt < 9; nt++)
#pragma unroll
        for (int i = 0; i < 4; i++) acc[nt][i] = 0.f;

    const int wbase = wid * 16;

    for (int kc = 0; kc < Hn; kc += 128) {
        // fill B chunk: 72 rows x 128 bf16 (16B segments)
        for (int e = tid; e < 72 * 16; e += 256) {
            int n = e >> 4, q = e & 15;
            *reinterpret_cast<uint4*>(&Bsm[n * AST + q * 8]) =
                *reinterpret_cast<const uint4*>(&g_WoutT[n * 512 + kc + q * 8]);
        }
        // fill A chunk: 128 rows x 128, tanh(p + ce), 4 elems/iter
        for (int e = tid; e < 128 * 32; e += 256) {
            int r = e >> 5;
            int col = (e & 31) * 4;
            int c = rc_c[r];
            int pb = rc_pb[r];
            float4 pe = *reinterpret_cast<const float4*>(&p[pb * 512 + kc + col]);
            float4 cv = *reinterpret_cast<const float4*>(&ce[(size_t)c * Hn + kc + col]);
            __nv_bfloat162 b0 = __floats2bfloat162_rn(tanh_fast(pe.x + cv.x),
                                                      tanh_fast(pe.y + cv.y));
            __nv_bfloat162 b1 = __floats2bfloat162_rn(tanh_fast(pe.z + cv.z),
                                                      tanh_fast(pe.w + cv.w));
            uint2 pk = make_uint2(*reinterpret_cast<uint32_t*>(&b0),
                                  *reinterpret_cast<uint32_t*>(&b1));
            *reinterpret_cast<uint2*>(&Asm[r * AST + col]) = pk;
        }
        __syncthreads();

        // MMA over this chunk: 8 k-steps of 16
#pragma unroll
        for (int kk = 0; kk < 8; kk++) {
            const int k0 = kk * 16;
            uint32_t bf[9][2];
#pragma unroll
            for (int nt = 0; nt < 9; nt++) {
                int n = nt * 8 + gq;
                bf[nt][0] = *reinterpret_cast<const uint32_t*>(&Bsm[n * AST + k0 + tg * 2]);
                bf[nt][1] = *reinterpret_cast<const uint32_t*>(&Bsm[n * AST + k0 + 8 + tg * 2]);
            }
            const int r0 = wbase + gq;
            uint32_t af[4];
            af[0] = *reinterpret_cast<const uint32_t*>(&Asm[r0 * AST + k0 + tg * 2]);
            af[1] = *reinterpret_cast<const uint32_t*>(&Asm[(r0 + 8) * AST + k0 + tg * 2]);
            af[2] = *reinterpret_cast<const uint32_t*>(&Asm[r0 * AST + k0 + 8 + tg * 2]);
            af[3] = *reinterpret_cast<const uint32_t*>(&Asm[(r0 + 8) * AST + k0 + 8 + tg * 2]);
#pragma unroll
            for (int nt = 0; nt < 9; nt++) mma16816(acc[nt], af, bf[nt]);
        }
        __syncthreads();   // done reading chunk before refill
    }

    // Stage D into SMEM (reuse dynamic region: 38 KB <= 54.4 KB)
    float* d_sm = reinterpret_cast<float*>(dynsmem);
    {
        const int r0 = wbase + gq;
#pragma unroll
        for (int nt = 0; nt < 9; nt++) {
            const int col = nt * 8 + tg * 2;
            d_sm[col * DSTRIDE + r0]           = acc[nt][0];
            d_sm[(col + 1) * DSTRIDE + r0]     = acc[nt][1];
            d_sm[col * DSTRIDE + r0 + 8]       = acc[nt][2];
            d_sm[(col + 1) * DSTRIDE + r0 + 8] = acc[nt][3];
        }
    }
    __syncthreads();

    for (int e = tid; e < Cn * 128; e += 256) {
        int k = e >> 7;
        int r = e & 127;
        g_den[(size_t)btc[r] + k * CSTRIDE] = __expf(d_sm[k * DSTRIDE + r]);
    }
}

// ---------------------------------------------------------------------------
// Kernel 2.5a: pairwise transition products via tf32 mma.sync (PROVEN R13).
// ---------------------------------------------------------------------------
__global__ __launch_bounds__(160) void k_pair(const int* __restrict__ nf) {
    __shared__ float D1s[72 * S1];
    __shared__ float D2s[72 * S2];

    const int tid = threadIdx.x;
    const int wid = tid >> 5;
    const int lane = tid & 31;
    const int gq = lane >> 2;
    const int tg = lane & 3;
    const int j = blockIdx.x;
    const int b = blockIdx.y;
    const int Tb = nf[b];
    const int t0 = 2 * j;
    if (t0 >= Tb) return;
    const bool single = (t0 + 1 >= Tb);

    const float* T1 = g_den + (size_t)(b * Tn + t0) * TILE_PAD;
    const float* T2 = single ? T1 : T1 + TILE_PAD;

    for (int i = tid; i < 72 * S1; i += 160) D1s[i] = 0.f;
    for (int i = tid; i < 72 * S2; i += 160) D2s[i] = 0.f;
    __syncthreads();

    for (int i = tid; i < 65 * 66; i += 160) {
        int r = i / 66, c = i - r * 66;
        D1s[r * S1 + c] = T1[i];
        D2s[r * S2 + c] = T2[i];
    }
    __syncthreads();

    if (tid < 65) {
        float b1 = T1[tid];
        float b2 = T2[tid];
        if (tid >= 1) {
            D1s[tid * S1 + tid] += b1;
            D2s[tid * S2 + tid] += b2;
        }
        D1s[tid] = (tid == 0) ? b1 : 0.f;
        D2s[tid] = (tid == 0) ? b2 : 0.f;
    }
    __syncthreads();

    float* outp = g_pair + (size_t)(b * 64 + j) * SLOT_PAD;

    if (single) {
        for (int i = tid; i < 65 * 66; i += 160) {
            int s = i / 66, c = i - s * 66;
            outp[i] = D1s[s * S1 + c];
        }
        return;
    }

    const int row0 = wid * 16 + gq;
    float acc[9][4];
#pragma unroll
    for (int nt = 0; nt < 9; nt++)
#pragma unroll
        for (int i = 0; i < 4; i++) acc[nt][i] = 0.f;

#pragma unroll
    for (int ks = 0; ks < 9; ks++) {
        const int k0 = ks * 8;
        uint32_t af[4];
        af[0] = to_tf32(D1s[(k0 + tg) * S1 + row0]);
        af[1] = to_tf32(D1s[(k0 + tg) * S1 + row0 + 8]);
        af[2] = to_tf32(D1s[(k0 + tg + 4) * S1 + row0]);
        af[3] = to_tf32(D1s[(k0 + tg + 4) * S1 + row0 + 8]);
        uint32_t bf[9][2];
#pragma unroll
        for (int nt = 0; nt < 9; nt++) {
            int sc = nt * 8 + gq;
            bf[nt][0] = to_tf32(D2s[sc * S2 + k0 + tg]);
            bf[nt][1] = to_tf32(D2s[sc * S2 + k0 + tg + 4]);
        }
#pragma unroll
        for (int nt = 0; nt < 9; nt++) mma_tf32(acc[nt], af, bf[nt]);
    }

#pragma unroll
    for (int nt = 0; nt < 9; nt++) {
        const int s0 = nt * 8 + tg * 2;
        if (row0 < 65) {
            if (s0 < 65)     outp[s0 * 66 + row0]       = acc[nt][0];
            if (s0 + 1 < 65) outp[(s0 + 1) * 66 + row0] = acc[nt][1];
        }
        if (row0 + 8 < 65) {
            if (s0 < 65)     outp[s0 * 66 + row0 + 8]       = acc[nt][2];
            if (s0 + 1 < 65) outp[(s0 + 1) * 66 + row0 + 8] = acc[nt][3];
        }
    }
}

// ---------------------------------------------------------------------------
// Kernel 2.5b: generic product level. lvl=1: g_pair->g_quad, lvl=2: g_quad->g_oct.
// ---------------------------------------------------------------------------
__global__ __launch_bounds__(160) void k_mul(const int* __restrict__ nf, int lvl) {
    __shared__ float D1s[72 * S1];
    __shared__ float D2s[72 * S2];

    const int tid = threadIdx.x;
    const int wid = tid >> 5;
    const int lane = tid & 31;
    const int gq = lane >> 2;
    const int tg = lane & 3;
    const int j = blockIdx.x;
    const int b = blockIdx.y;
    const int Tb = nf[b];
    const int n_src = (Tb + (1 << lvl) - 1) >> lvl;
    if (2 * j >= n_src) return;
    const bool single = (2 * j + 1 >= n_src);

    const int smax = (lvl == 1) ? 64 : 32;
    const float* srcb = (lvl == 1) ? g_pair : g_quad;
    float* dstb = (lvl == 1) ? g_quad : g_oct;
    const float* A = srcb + (size_t)(b * smax + 2 * j) * SLOT_PAD;
    const float* Bt = A + SLOT_PAD;
    float* outp = dstb + (size_t)(b * (smax >> 1) + j) * SLOT_PAD;

    if (single) {
        for (int i = tid; i < 65 * 66; i += 160) outp[i] = A[i];
        return;
    }

    for (int i = tid; i < 7 * S1; i += 160) D1s[65 * S1 + i] = 0.f;
    for (int i = tid; i < 65 * 6; i += 160) {
        int r = i / 6;
        D2s[r * S2 + 66 + (i - r * 6)] = 0.f;
    }
    for (int i = tid; i < 65 * 33; i += 160) {
        int r = i / 33, c2 = (i - r * 33) * 2;
        *reinterpret_cast<float2*>(&D1s[r * S1 + c2]) =
            *reinterpret_cast<const float2*>(&A[r * 66 + c2]);
        *reinterpret_cast<float2*>(&D2s[r * S2 + c2]) =
            *reinterpret_cast<const float2*>(&Bt[r * 66 + c2]);
    }
    __syncthreads();

    const int row0 = wid * 16 + gq;
    float acc[9][4];
#pragma unroll
    for (int nt = 0; nt < 9; nt++)
#pragma unroll
        for (int i = 0; i < 4; i++) acc[nt][i] = 0.f;

#pragma unroll
    for (int ks = 0; ks < 9; ks++) {
        const int k0 = ks * 8;
        uint32_t af[4];
        af[0] = to_tf32(D1s[(k0 + tg) * S1 + row0]);
        af[1] = to_tf32(D1s[(k0 + tg) * S1 + row0 + 8]);
        af[2] = to_tf32(D1s[(k0 + tg + 4) * S1 + row0]);
        af[3] = to_tf32(D1s[(k0 + tg + 4) * S1 + row0 + 8]);
        uint32_t bf[9][2];
#pragma unroll
        for (int nt = 0; nt < 9; nt++) {
            int sc = nt * 8 + gq;
            bf[nt][0] = to_tf32(D2s[sc * S2 + k0 + tg]);
            bf[nt][1] = to_tf32(D2s[sc * S2 + k0 + tg + 4]);
        }
#pragma unroll
        for (int nt = 0; nt < 9; nt++) mma_tf32(acc[nt], af, bf[nt]);
    }

#pragma unroll
    for (int nt = 0; nt < 9; nt++) {
        const int s0 = nt * 8 + tg * 2;
        if (row0 < 65) {
            if (s0 < 65)     outp[s0 * 66 + row0]       = acc[nt][0];
            if (s0 + 1 < 65) outp[(s0 + 1) * 66 + row0] = acc[nt][1];
        }
        if (row0 + 8 < 65) {
            if (s0 < 65)     outp[s0 * 66 + row0 + 8]       = acc[nt][2];
            if (s0 + 1 < 65) outp[(s0 + 1) * 66 + row0 + 8] = acc[nt][3];
        }
    }
}

// ---------------------------------------------------------------------------
// Kernel 3: warp-specialized scan over OCT tiles (<=16 steps). 224 threads.
// ---------------------------------------------------------------------------
__global__ __launch_bounds__(224) void k_scan(const int* __restrict__ num_frames,
                                              const int* __restrict__ labels,
                                              const int* __restrict__ num_labels,
                                              float* __restrict__ out) {
    extern __shared__ __align__(16) float tilebuf[];   // 4 * SLOT_PAD floats
    __shared__ __align__(16) float beta_sh[2][68];
    __shared__ float maxw[2];
    __shared__ float nm_fin[Un + 1];
    __shared__ int ne_fin[Un + 1];
    __shared__ int esum_sh;
    __shared__ __align__(8) unsigned long long mbars[8];   // full[0..3], empty[4..7]

    const int b = blockIdx.x;
    const int tid = threadIdx.x;
    const int wid = tid >> 5;
    const int lane = tid & 31;
    const int Tb = num_frames[b];          // in [64, 128]
    const int To = (Tb + 7) >> 3;          // oct steps, in [8, 16]

    uint32_t mb_full[4], mb_empty[4];
#pragma unroll
    for (int s = 0; s < 4; s++) {
        mb_full[s] = smem_u32(&mbars[s]);
        mb_empty[s] = smem_u32(&mbars[4 + s]);
    }
    if (tid == 0) {
#pragma unroll
        for (int s = 0; s < 4; s++) {
            MBAR_INIT(mb_full[s], 32);
            MBAR_INIT(mb_empty[s], 2);
        }
    }
    if (tid < 68) {
        beta_sh[0][tid] = (tid == 0) ? 1.f : 0.f;
        beta_sh[1][tid] = 0.f;
    }
    __syncthreads();

    const float* pbase = g_oct + (size_t)(b * 16) * SLOT_PAD;

    if (wid >= 3) {
        const int p = wid - 3;
        const uint32_t dst0 = smem_u32(tilebuf) + p * SLOT_BYTES;
        int eph = 1;
        for (int pp = p; pp < To; pp += 4) {
            mbar_wait(mb_empty[p], (uint32_t)eph);
            eph ^= 1;
            const float* src = pbase + (size_t)pp * SLOT_PAD;
#pragma unroll
            for (int i = lane; i < SLOT_PAD / 4; i += 32)
                cp_async16(dst0 + i * 16, src + i * 4);
            CP_COMMIT();
            CP_WAIT0();
            MBAR_ARRIVE(mb_full[p]);
        }
    } else if (wid < 2) {
        const int st = wid * 32 + lane;
        const bool ex = (wid == 1 && lane == 31);
        const int rowoff = st * CSTRIDE;
        float nv64 = 0.f;
        int esum = 0;

        for (int pp = 0; pp < To; pp++) {
            const int s = pp & 3;
            mbar_wait(mb_full[s], (uint32_t)((pp >> 2) & 1));
            const float* Tt = tilebuf + s * SLOT_PAD;
            const float* bsh = beta_sh[pp & 1];
            const float2* b2 = reinterpret_cast<const float2*>(bsh);

            const float2* r2 = reinterpret_cast<const float2*>(Tt + rowoff);
            float s0 = 0.f, s1 = 0.f, s2 = 0.f, s3 = 0.f;
#pragma unroll 8
            for (int c2 = 0; c2 < 32; c2 += 2) {
                float2 a0 = r2[c2],     w0v = b2[c2];
                float2 a1 = r2[c2 + 1], w1v = b2[c2 + 1];
                s0 += a0.x * w0v.x; s1 += a0.y * w0v.y;
                s2 += a1.x * w1v.x; s3 += a1.y * w1v.y;
            }
            {
                float2 a32 = r2[32], w32 = b2[32];
                s0 += a32.x * w32.x; s1 += a32.y * w32.y;
            }
            float nv = (s0 + s1) + (s2 + s3);

            if (ex) {
                const float2* r64 = reinterpret_cast<const float2*>(Tt + 64 * CSTRIDE);
                float t0 = 0.f, t1 = 0.f;
#pragma unroll 8
                for (int c2 = 0; c2 < 32; c2++) {
                    float2 a0 = r64[c2], w0v = b2[c2];
                    t0 += a0.x * w0v.x; t1 += a0.y * w0v.y;
                }
                float2 a32 = r64[32], w32 = b2[32];
                nv64 = t0 + t1 + a32.x * w32.x + a32.y * w32.y;
            }

            __syncwarp();
            if (lane == 0) MBAR_ARRIVE(mb_empty[s]);

            {
                float mx = ex ? fmaxf(nv, nv64) : nv;
#pragma unroll
                for (int o = 16; o; o >>= 1)
                    mx = fmaxf(mx, __shfl_xor_sync(0xffffffffu, mx, o));
                if (lane == 0) maxw[wid] = mx;
                asm volatile("bar.sync 1, 64;" ::: "memory");
                float gm = fmaxf(maxw[0], maxw[1]);
                int eb = ((__float_as_int(gm) >> 23) & 0xFF) - 127;
                float sc = exp2i(-eb);
                nv *= sc; nv64 *= sc; esum += eb;
            }

            beta_sh[1 - (pp & 1)][st] = nv;
            if (ex) beta_sh[1 - (pp & 1)][64] = nv64;
            asm volatile("bar.sync 1, 64;" ::: "memory");
        }
        if (tid == 0) esum_sh = esum;
    } else {
        // numerator (warp 2): static-indexed 4-deep register ring over g_den
        const float* base = g_den + (size_t)(b * Tn) * TILE_PAD;
        const int* lb = labels + b * Un;
        const int j = lane;
        const int cj = (j == 0) ? 0 : lb[j - 1];
        const int cm = (j >= 2) ? lb[j - 2] : 0;
        const int c32 = lb[31], c31 = lb[30];
        const bool l0 = (j == 0);
        float m = l0 ? 1.f : 0.f;
        int e = l0 ? 0 : EMIN;
        float m2 = 0.f;
        int e2 = EMIN;

        const float* gA = base + cj;
        const float* gB = base + cj * CSTRIDE + cm;
        const float* gC = base + c32;
        const float* gD = base + c32 * CSTRIDE + c31;

        float va[4], vb[4], vc[4], vd[4];
#pragma unroll
        for (int k = 0; k < 4; k++) {
            size_t o = (size_t)k * TILE_PAD;
            va[k] = gA[o];
            vb[k] = (j > 0) ? gB[o] : 0.f;
            vc[k] = l0 ? gC[o] : 0.f;
            vd[k] = l0 ? gD[o] : 0.f;
        }

        for (int tb = 0; tb < Tb; tb += 4) {
            float na[4], nb[4], nc[4], nd[4];
#pragma unroll
            for (int k = 0; k < 4; k++) {
                int tt = tb + 4 + k;
                if (tt > Tb - 1) tt = Tb - 1;
                size_t o = (size_t)tt * TILE_PAD;
                na[k] = gA[o];
                nb[k] = (j > 0) ? gB[o] : 0.f;
                nc[k] = l0 ? gC[o] : 0.f;
                nd[k] = l0 ? gD[o] : 0.f;
            }
#pragma unroll
            for (int k = 0; k < 4; k++) {
                if (tb + k < Tb) {
                    float mp = __shfl_up_sync(0xffffffffu, m, 1);
                    int epv = __shfl_up_sync(0xffffffffu, e, 1);
                    float m31 = __shfl_sync(0xffffffffu, m, 31);
                    int e31 = __shfl_sync(0xffffffffu, e, 31);

                    float own = m * va[k];
                    float oth = (j > 0) ? mp * vb[k] : 0.f;
                    int epo = (j > 0) ? epv : EMIN;
                    accum2(own, e, oth, epo, m, e);

                    if (l0) {
                        float own2 = m2 * vc[k];
                        float oth2 = m31 * vd[k];
                        accum2(own2, e2, oth2, e31, m2, e2);
                    }
                }
            }
#pragma unroll
            for (int k = 0; k < 4; k++) { va[k] = na[k]; vb[k] = nb[k]; vc[k] = nc[k]; vd[k] = nd[k]; }
        }
        nm_fin[j] = m;
        ne_fin[j] = e;
        if (l0) { nm_fin[32] = m2; ne_fin[32] = e2; }
    }

    __syncthreads();
    if (tid == 0) {
        const float* bf = beta_sh[To & 1];
        float ssum = 0.f;
        for (int c = 0; c < Cn; c++) ssum += bf[c];
        float den = (float)esum_sh * LN2F + __logf(ssum);
        int nl = num_labels[b];
        float num = __logf(nm_fin[nl]) + (float)ne_fin[nl] * LN2F;
        out[b] = den - num;
    }
}

// ---------------------------------------------------------------------------
extern "C" void kernel_launch(void* const* d_in, const int* in_sizes, int n_in,
                              void* d_out, int out_size) {
    const float* frames = (const float*)d_in[0];   // (8,128,512)
    const float* Wf     = (const float*)d_in[1];   // (512,512)
    const float* ce     = (const float*)d_in[2];   // (65,512)
    const float* Wo     = (const float*)d_in[3];   // (512,65)
    const int* nf       = (const int*)d_in[4];     // (8,)
    const int* labels   = (const int*)d_in[5];     // (8,32)
    const int* nl       = (const int*)d_in[6];     // (8,)
    float* out = (float*)d_out;                    // (8,)

    cudaFuncSetAttribute(k_logits, cudaFuncAttributeMaxDynamicSharedMemorySize, DYN_SMEM);
    cudaFuncSetAttribute(k_scan, cudaFuncAttributeMaxDynamicSharedMemorySize, SCAN_SMEM);

    k_prep<<<4, 256>>>(Wo);
    k_proj<<<dim3(Hn / 32, (Bn * Tn) / 64), 128>>>(frames, Wf);
    k_logits<<<NB_LOGITS, 256, DYN_SMEM>>>(ce);
    k_pair<<<dim3(64, Bn), 160>>>(nf);
    k_mul<<<dim3(32, Bn), 160>>>(nf, 1);
    k_mul<<<dim3(16, Bn), 160>>>(nf, 2);
    k_scan<<<Bn, 224, SCAN_SMEM>>>(nf, labels, nl, out);
}

// round 17
// speedup vs baseline: 1.1549x; 1.0345x over previous
#include <cuda_runtime.h>
#include <cuda_bf16.h>
#include <math.h>
#include <stdint.h>

#define NEG_INF (-1e30f)

// Problem constants
#define Bn 8
#define Tn 128
#define Dn 512
#define Hn 512
#define Vn 64
#define Un 32
#define Cn 65          // V + 1
#define CSTRIDE 66     // row stride of tiles; pads (c=65) provably zero
#define TILE_PAD 4352  // g_den per-(b,t) tile floats (>= 65*66=4290)
#define SLOT_PAD 4480  // per-slot floats for product tiles (>= 66*66), 16B mult
#define SLOT_BYTES (SLOT_PAD * 4)   // 17920
#define MROWS (Bn * Tn * Cn)        // 66560 = 260 * 256
#define NB_LOGITS (MROWS / 256)     // 260

// k_logits chunked tile geometry (bf16 elems), M=256 rows/block
#define AST 136                     // chunk row stride (128 data + 8 pad)
#define A_CH (256 * AST)            // 34816 elems = 69632 B
#define B_CH (72 * AST)             //  9792 elems = 19584 B
#define DYN_SMEM ((A_CH + B_CH) * 2)   // 89216 B -> 2 blocks/SM, 260 blocks = 1 wave
#define DST2 260                    // fp32 stage stride (8*tg+gq distinct -> conflict-free)

#define SCAN_SMEM (4 * SLOT_BYTES)  // 71680 B ring
#define EMIN (-(1 << 28))
#define LN2F 0.69314718055994531f

// product-kernel SMEM strides (bank-conflict-free fragment reads; proven R13)
#define S1 88   // D1s[m][c] : A reads conflict-free
#define S2 76   // D2s[s][k] : B reads conflict-free

// Scratch (__device__ globals; zero-initialized, 16B-aligned)
__device__ __align__(16) float g_proj[Bn * Tn * Hn];
__device__ __align__(16) float g_den[Bn * Tn * TILE_PAD];      // [bt][k*66+c] = exp(logit); pads 0
__device__ __align__(16) float g_pair[Bn * 64 * SLOT_PAD];     // 2-step products
__device__ __align__(16) float g_quad[Bn * 32 * SLOT_PAD];     // 4-step products
__device__ __align__(16) float g_oct [Bn * 16 * SLOT_PAD];     // 8-step products
__device__ __align__(16) __nv_bfloat16 g_WoutT[72 * 512];

// ---------------------------------------------------------------------------
__device__ __forceinline__ float tanh_fast(float x) {
    float y; asm("tanh.approx.f32 %0, %1;" : "=f"(y) : "f"(x)); return y;
}
__device__ __forceinline__ uint32_t smem_u32(const void* p) {
    uint32_t a;
    asm("{ .reg .u64 t; cvta.to.shared.u64 t, %1; cvt.u32.u64 %0, t; }" : "=r"(a) : "l"(p));
    return a;
}
__device__ __forceinline__ void cp_async16(uint32_t saddr, const void* g) {
    asm volatile("cp.async.cg.shared.global [%0], [%1], 16;" :: "r"(saddr), "l"(g));
}
#define CP_COMMIT() asm volatile("cp.async.commit_group;" ::: "memory")
#define CP_WAIT0()  asm volatile("cp.async.wait_group 0;" ::: "memory")
#define CP_WAIT1()  asm volatile("cp.async.wait_group 1;" ::: "memory")

#define MBAR_INIT(addr, cnt) \
    asm volatile("mbarrier.init.shared.b64 [%0], %1;" :: "r"(addr), "r"((uint32_t)(cnt)) : "memory")
#define MBAR_ARRIVE(addr) \
    asm volatile("mbarrier.arrive.shared.b64 _, [%0];" :: "r"(addr) : "memory")

__device__ __forceinline__ void mbar_wait(uint32_t addr, uint32_t phase) {
    asm volatile(
        "{\n\t.reg .pred P;\n\t"
        "LW_%=:\n\t"
        "mbarrier.try_wait.parity.acquire.cta.shared::cta.b64 P, [%0], %1, 0x989680;\n\t"
        "@P bra.uni LD_%=;\n\t"
        "bra.uni LW_%=;\n\t"
        "LD_%=:\n\t}"
        :: "r"(addr), "r"(phase) : "memory");
}

__device__ __forceinline__ void mma16816(float* c, const uint32_t* a, const uint32_t* b) {
    asm volatile(
        "mma.sync.aligned.m16n8k16.row.col.f32.bf16.bf16.f32 "
        "{%0,%1,%2,%3}, {%4,%5,%6,%7}, {%8,%9}, {%0,%1,%2,%3};"
        : "+f"(c[0]), "+f"(c[1]), "+f"(c[2]), "+f"(c[3])
        : "r"(a[0]), "r"(a[1]), "r"(a[2]), "r"(a[3]), "r"(b[0]), "r"(b[1]));
}
__device__ __forceinline__ uint32_t to_tf32(float f) {
    uint32_t u; asm("cvt.rna.tf32.f32 %0, %1;" : "=r"(u) : "f"(f)); return u;
}
__device__ __forceinline__ void mma_tf32(float* c, const uint32_t* a, const uint32_t* b) {
    asm volatile(
        "mma.sync.aligned.m16n8k8.row.col.f32.tf32.tf32.f32 "
        "{%0,%1,%2,%3}, {%4,%5,%6,%7}, {%8,%9}, {%0,%1,%2,%3};"
        : "+f"(c[0]), "+f"(c[1]), "+f"(c[2]), "+f"(c[3])
        : "r"(a[0]), "r"(a[1]), "r"(a[2]), "r"(a[3]), "r"(b[0]), "r"(b[1]));
}

// 2^d for d in [-127, 127], exact, branchless
__device__ __forceinline__ float exp2i(int d) {
    return __int_as_float((d + 127) << 23);
}
// (m,e) <- own*2^eo + oth*2^ep, with own,oth >= 0; m in [1,2) or 0.
__device__ __forceinline__ void accum2(float own, int eo, float oth, int ep,
                                       float& m, int& e) {
    int base = (eo > ep) ? eo : ep;
    int d0 = eo - base; d0 = (d0 < -127) ? -127 : d0;
    int d1 = ep - base; d1 = (d1 < -127) ? -127 : d1;
    float nn = own * exp2i(d0) + oth * exp2i(d1);
    if (nn > 0.f) {
        int bits = __float_as_int(nn);
        e = base + ((bits >> 23) & 0xFF) - 127;
        m = __int_as_float((bits & 0x007FFFFF) | 0x3F800000);
    } else {
        m = 0.f; e = EMIN;
    }
}

// ---------------------------------------------------------------------------
// Kernel 0: transpose + bf16-convert Wout -> g_WoutT[n][k]  (rows n>=65 zero)
// ---------------------------------------------------------------------------
__global__ void k_prep(const float* __restrict__ Wo) {
    const int tid = threadIdx.x + blockIdx.x * blockDim.x;
    for (int e = tid; e < 72 * 512; e += blockDim.x * gridDim.x) {
        int n = e >> 9;
        int k = e & 511;
        float v = (n < Cn) ? Wo[k * Cn + n] : 0.f;
        g_WoutT[e] = __float2bfloat16(v);
    }
}

// ---------------------------------------------------------------------------
// Kernel 1: proj = frames @ W_frame via tf32 mma.sync (m16n8k8).
// ---------------------------------------------------------------------------
#define PAS 36

__global__ __launch_bounds__(128) void k_proj(const float* __restrict__ A,
                                              const float* __restrict__ Bm) {
    __shared__ __align__(16) float As2[2][64 * PAS];
    __shared__ __align__(16) float Bs2[2][32 * PAS];

    const int tid = threadIdx.x;
    const int wid = tid >> 5;
    const int lane = tid & 31;
    const int gq = lane >> 2;
    const int tg = lane & 3;
    const int bm = blockIdx.y * 64;
    const int bn = blockIdx.x * 32;
    const int wm = (wid >> 1) * 32;
    const int wn = (wid & 1) * 16;

    const uint32_t asb[2] = { smem_u32(As2[0]), smem_u32(As2[1]) };
    const uint32_t bsb[2] = { smem_u32(Bs2[0]), smem_u32(Bs2[1]) };

    auto issue = [&](int ch, int buf) {
        const int kc = ch * 32;
#pragma unroll
        for (int l = 0; l < 4; l++) {
            int o = tid + l * 128;
            int row = o >> 3, seg = o & 7;
            cp_async16(asb[buf] + (row * PAS + seg * 4) * 4,
                       A + (size_t)(bm + row) * Dn + kc + seg * 4);
        }
#pragma unroll
        for (int l = 0; l < 2; l++) {
            int o = tid + l * 128;
            int kr = o >> 3, seg = o & 7;
            cp_async16(bsb[buf] + (kr * PAS + seg * 4) * 4,
                       Bm + (size_t)(kc + kr) * Hn + bn + seg * 4);
        }
        CP_COMMIT();
    };

    float acc[2][2][4];
#pragma unroll
    for (int mt = 0; mt < 2; mt++)
#pragma unroll
        for (int nt = 0; nt < 2; nt++)
#pragma unroll
            for (int i = 0; i < 4; i++) acc[mt][nt][i] = 0.f;

    issue(0, 0);

    for (int ch = 0; ch < 16; ch++) {
        const int buf = ch & 1;
        if (ch + 1 < 16) { issue(ch + 1, 1 - buf); CP_WAIT1(); }
        else             { CP_WAIT0(); }
        __syncthreads();

        const float* As = As2[buf];
        const float* Bs = Bs2[buf];
#pragma unroll
        for (int ks = 0; ks < 4; ks++) {
            const int k0 = ks * 8;
            uint32_t bf[2][2];
#pragma unroll
            for (int nt = 0; nt < 2; nt++) {
                int cb = wn + nt * 8 + gq;
                bf[nt][0] = to_tf32(Bs[(k0 + tg) * PAS + cb]);
                bf[nt][1] = to_tf32(Bs[(k0 + tg + 4) * PAS + cb]);
            }
#pragma unroll
            for (int mt = 0; mt < 2; mt++) {
                int rm = wm + mt * 16 + gq;
                uint32_t af[4];
                af[0] = to_tf32(As[rm * PAS + k0 + tg]);
                af[1] = to_tf32(As[(rm + 8) * PAS + k0 + tg]);
                af[2] = to_tf32(As[rm * PAS + k0 + tg + 4]);
                af[3] = to_tf32(As[(rm + 8) * PAS + k0 + tg + 4]);
#pragma unroll
                for (int nt = 0; nt < 2; nt++) mma_tf32(acc[mt][nt], af, bf[nt]);
            }
        }
        __syncthreads();
    }

#pragma unroll
    for (int mt = 0; mt < 2; mt++) {
        int row = bm + wm + mt * 16 + gq;
#pragma unroll
        for (int nt = 0; nt < 2; nt++) {
            int col = bn + wn + nt * 8 + tg * 2;
            *reinterpret_cast<float2*>(&g_proj[(size_t)row * Hn + col]) =
                make_float2(acc[mt][nt][0], acc[mt][nt][1]);
            *reinterpret_cast<float2*>(&g_proj[(size_t)(row + 8) * Hn + col]) =
                make_float2(acc[mt][nt][2], acc[mt][nt][3]);
        }
    }
}

// ---------------------------------------------------------------------------
// Kernel 2: logits via mma.sync bf16 (m16n8k16), 256 threads (8 warps).
// M=256 rows/block (260 blocks = exactly 1 wave at 2 blocks/SM), K-chunked
// (4 chunks of 128). Stores EXP of logits transposed: g_den[bt][k*66 + c].
// ---------------------------------------------------------------------------
__global__ __launch_bounds__(256) void k_logits(const float* __restrict__ ce) {
    extern __shared__ __align__(16) __nv_bfloat16 dynsmem[];
    __nv_bfloat16* Asm = dynsmem;             // [256][AST]
    __nv_bfloat16* Bsm = dynsmem + A_CH;      // [72][AST]
    __shared__ __align__(16) float p[5 * 512];
    __shared__ int btc[256];                  // output base offsets
    __shared__ short rc_c[256], rc_pb[256];   // row -> (c, proj-slot)

    const int tid = threadIdx.x;
    const int wid = tid >> 5;
    const int lane = tid & 31;
    const int gq = lane >> 2;
    const int tg = lane & 3;
    const int g0 = blockIdx.x * 256;
    const int bt0 = g0 / 65;

    for (int i = tid; i < 5 * 512; i += 256) {
        int bt = bt0 + (i >> 9);
        p[i] = (bt < Bn * Tn) ? g_proj[(size_t)bt * Hn + (i & 511)] : 0.f;
    }
    {
        int bt = (g0 + tid) / 65;
        int c = g0 + tid - bt * 65;
        btc[tid] = bt * TILE_PAD + c;
        rc_c[tid] = (short)c;
        rc_pb[tid] = (short)(bt - bt0);
    }
    __syncthreads();

    float acc[2][9][4];
#pragma unroll
    for (int mt = 0; mt < 2; mt++)
#pragma unroll
        for (int nt = 0; nt < 9; nt++)
#pragma unroll
            for (int i = 0; i < 4; i++) acc[mt][nt][i] = 0.f;

    const int wbase = wid * 32;

    for (int kc = 0; kc < Hn; kc += 128) {
        // fill B chunk: 72 rows x 128 bf16 (16B segments)
        for (int e = tid; e < 72 * 16; e += 256) {
            int n = e >> 4, q = e & 15;
            *reinterpret_cast<uint4*>(&Bsm[n * AST + q * 8]) =
                *reinterpret_cast<const uint4*>(&g_WoutT[n * 512 + kc + q * 8]);
        }
        // fill A chunk: 256 rows x 128, tanh(p + ce), 4 elems/iter
        for (int e = tid; e < 256 * 32; e += 256) {
            int r = e >> 5;
            int col = (e & 31) * 4;
            int c = rc_c[r];
            int pb = rc_pb[r];
            float4 pe = *reinterpret_cast<const float4*>(&p[pb * 512 + kc + col]);
            float4 cv = *reinterpret_cast<const float4*>(&ce[(size_t)c * Hn + kc + col]);
            __nv_bfloat162 b0 = __floats2bfloat162_rn(tanh_fast(pe.x + cv.x),
                                                      tanh_fast(pe.y + cv.y));
            __nv_bfloat162 b1 = __floats2bfloat162_rn(tanh_fast(pe.z + cv.z),
                                                      tanh_fast(pe.w + cv.w));
            uint2 pk = make_uint2(*reinterpret_cast<uint32_t*>(&b0),
                                  *reinterpret_cast<uint32_t*>(&b1));
            *reinterpret_cast<uint2*>(&Asm[r * AST + col]) = pk;
        }
        __syncthreads();

        // MMA over this chunk: 8 k-steps of 16, 2 m-tiles per warp
#pragma unroll
        for (int kk = 0; kk < 8; kk++) {
            const int k0 = kk * 16;
            uint32_t bf[9][2];
#pragma unroll
            for (int nt = 0; nt < 9; nt++) {
                int n = nt * 8 + gq;
                bf[nt][0] = *reinterpret_cast<const uint32_t*>(&Bsm[n * AST + k0 + tg * 2]);
                bf[nt][1] = *reinterpret_cast<const uint32_t*>(&Bsm[n * AST + k0 + 8 + tg * 2]);
            }
#pragma unroll
            for (int mt = 0; mt < 2; mt++) {
                const int r0 = wbase + mt * 16 + gq;
                uint32_t af[4];
                af[0] = *reinterpret_cast<const uint32_t*>(&Asm[r0 * AST + k0 + tg * 2]);
                af[1] = *reinterpret_cast<const uint32_t*>(&Asm[(r0 + 8) * AST + k0 + tg * 2]);
                af[2] = *reinterpret_cast<const uint32_t*>(&Asm[r0 * AST + k0 + 8 + tg * 2]);
                af[3] = *reinterpret_cast<const uint32_t*>(&Asm[(r0 + 8) * AST + k0 + 8 + tg * 2]);
#pragma unroll
                for (int nt = 0; nt < 9; nt++) mma16816(acc[mt][nt], af, bf[nt]);
            }
        }
        __syncthreads();   // done reading chunk before refill
    }

    // Stage D into SMEM (reuse dynamic region: 72*DST2*4 = 74.9 KB <= 89 KB)
    float* d_sm = reinterpret_cast<float*>(dynsmem);
#pragma unroll
    for (int mt = 0; mt < 2; mt++) {
        const int r0 = wbase + mt * 16 + gq;
#pragma unroll
        for (int nt = 0; nt < 9; nt++) {
            const int col = nt * 8 + tg * 2;
            d_sm[col * DST2 + r0]           = acc[mt][nt][0];
            d_sm[(col + 1) * DST2 + r0]     = acc[mt][nt][1];
            d_sm[col * DST2 + r0 + 8]       = acc[mt][nt][2];
            d_sm[(col + 1) * DST2 + r0 + 8] = acc[mt][nt][3];
        }
    }
    __syncthreads();

    for (int e = tid; e < Cn * 256; e += 256) {
        int k = e >> 8;
        int r = e & 255;
        g_den[(size_t)btc[r] + k * CSTRIDE] = __expf(d_sm[k * DST2 + r]);
    }
}

// ---------------------------------------------------------------------------
// Kernel 2.5a: pairwise transition products via tf32 mma.sync.
// Staging now FLOAT2 (k_mul pattern) + densify fixups. Garbage in unstored
// C rows/cols is harmless (all stores guarded); K-pads zeroed on both sides.
// ---------------------------------------------------------------------------
__global__ __launch_bounds__(160) void k_pair(const int* __restrict__ nf) {
    __shared__ float D1s[72 * S1];
    __shared__ float D2s[72 * S2];

    const int tid = threadIdx.x;
    const int wid = tid >> 5;
    const int lane = tid & 31;
    const int gq = lane >> 2;
    const int tg = lane & 3;
    const int j = blockIdx.x;
    const int b = blockIdx.y;
    const int Tb = nf[b];
    const int t0 = 2 * j;
    if (t0 >= Tb) return;
    const bool single = (t0 + 1 >= Tb);

    const float* T1 = g_den + (size_t)(b * Tn + t0) * TILE_PAD;
    const float* T2 = single ? T1 : T1 + TILE_PAD;

    // zero K-pads: D1s rows 65..71 (full), D2s cols 65..75 of rows 0..71
    for (int i = tid; i < 7 * S1; i += 160) D1s[65 * S1 + i] = 0.f;
    for (int i = tid; i < 72 * 11; i += 160) {
        int r = i / 11;
        D2s[r * S2 + 65 + (i - r * 11)] = 0.f;
    }
    // straight float2 copies (col 65 of src is pad zero)
    for (int i = tid; i < 65 * 33; i += 160) {
        int r = i / 33, c2 = (i - r * 33) * 2;
        *reinterpret_cast<float2*>(&D1s[r * S1 + c2]) =
            *reinterpret_cast<const float2*>(&T1[r * 66 + c2]);
        *reinterpret_cast<float2*>(&D2s[r * S2 + c2]) =
            *reinterpret_cast<const float2*>(&T2[r * 66 + c2]);
    }
    __syncthreads();

    // densify fixups
    if (tid < 65) {
        float b1 = T1[tid];
        float b2 = T2[tid];
        if (tid >= 1) {
            D1s[tid * S1 + tid] += b1;
            D2s[tid * S2 + tid] += b2;
        }
        D1s[tid] = (tid == 0) ? b1 : 0.f;
        D2s[tid] = (tid == 0) ? b2 : 0.f;
    }
    __syncthreads();

    float* outp = g_pair + (size_t)(b * 64 + j) * SLOT_PAD;

    if (single) {
        for (int i = tid; i < 65 * 66; i += 160) {
            int s = i / 66, c = i - s * 66;
            outp[i] = D1s[s * S1 + c];
        }
        return;
    }

    const int row0 = wid * 16 + gq;
    float acc[9][4];
#pragma unroll
    for (int nt = 0; nt < 9; nt++)
#pragma unroll
        for (int i = 0; i < 4; i++) acc[nt][i] = 0.f;

#pragma unroll
    for (int ks = 0; ks < 9; ks++) {
        const int k0 = ks * 8;
        uint32_t af[4];
        af[0] = to_tf32(D1s[(k0 + tg) * S1 + row0]);
        af[1] = to_tf32(D1s[(k0 + tg) * S1 + row0 + 8]);
        af[2] = to_tf32(D1s[(k0 + tg + 4) * S1 + row0]);
        af[3] = to_tf32(D1s[(k0 + tg + 4) * S1 + row0 + 8]);
        uint32_t bf[9][2];
#pragma unroll
        for (int nt = 0; nt < 9; nt++) {
            int sc = nt * 8 + gq;
            bf[nt][0] = to_tf32(D2s[sc * S2 + k0 + tg]);
            bf[nt][1] = to_tf32(D2s[sc * S2 + k0 + tg + 4]);
        }
#pragma unroll
        for (int nt = 0; nt < 9; nt++) mma_tf32(acc[nt], af, bf[nt]);
    }

#pragma unroll
    for (int nt = 0; nt < 9; nt++) {
        const int s0 = nt * 8 + tg * 2;
        if (row0 < 65) {
            if (s0 < 65)     outp[s0 * 66 + row0]       = acc[nt][0];
            if (s0 + 1 < 65) outp[(s0 + 1) * 66 + row0] = acc[nt][1];
        }
        if (row0 + 8 < 65) {
            if (s0 < 65)     outp[s0 * 66 + row0 + 8]       = acc[nt][2];
            if (s0 + 1 < 65) outp[(s0 + 1) * 66 + row0 + 8] = acc[nt][3];
        }
    }
}

// ---------------------------------------------------------------------------
// Kernel 2.5b: generic product level. lvl=1: g_pair->g_quad, lvl=2: g_quad->g_oct.
// ---------------------------------------------------------------------------
__global__ __launch_bounds__(160) void k_mul(const int* __restrict__ nf, int lvl) {
    __shared__ float D1s[72 * S1];
    __shared__ float D2s[72 * S2];

    const int tid = threadIdx.x;
    const int wid = tid >> 5;
    const int lane = tid & 31;
    const int gq = lane >> 2;
    const int tg = lane & 3;
    const int j = blockIdx.x;
    const int b = blockIdx.y;
    const int Tb = nf[b];
    const int n_src = (Tb + (1 << lvl) - 1) >> lvl;
    if (2 * j >= n_src) return;
    const bool single = (2 * j + 1 >= n_src);

    const int smax = (lvl == 1) ? 64 : 32;
    const float* srcb = (lvl == 1) ? g_pair : g_quad;
    float* dstb = (lvl == 1) ? g_quad : g_oct;
    const float* A = srcb + (size_t)(b * smax + 2 * j) * SLOT_PAD;
    const float* Bt = A + SLOT_PAD;
    float* outp = dstb + (size_t)(b * (smax >> 1) + j) * SLOT_PAD;

    if (single) {
        for (int i = tid; i < 65 * 66; i += 160) outp[i] = A[i];
        return;
    }

    for (int i = tid; i < 7 * S1; i += 160) D1s[65 * S1 + i] = 0.f;
    for (int i = tid; i < 65 * 6; i += 160) {
        int r = i / 6;
        D2s[r * S2 + 66 + (i - r * 6)] = 0.f;
    }
    for (int i = tid; i < 65 * 33; i += 160) {
        int r = i / 33, c2 = (i - r * 33) * 2;
        *reinterpret_cast<float2*>(&D1s[r * S1 + c2]) =
            *reinterpret_cast<const float2*>(&A[r * 66 + c2]);
        *reinterpret_cast<float2*>(&D2s[r * S2 + c2]) =
            *reinterpret_cast<const float2*>(&Bt[r * 66 + c2]);
    }
    __syncthreads();

    const int row0 = wid * 16 + gq;
    float acc[9][4];
#pragma unroll
    for (int nt = 0; nt < 9; nt++)
#pragma unroll
        for (int i = 0; i < 4; i++) acc[nt][i] = 0.f;

#pragma unroll
    for (int ks = 0; ks < 9; ks++) {
        const int k0 = ks * 8;
        uint32_t af[4];
        af[0] = to_tf32(D1s[(k0 + tg) * S1 + row0]);
        af[1] = to_tf32(D1s[(k0 + tg) * S1 + row0 + 8]);
        af[2] = to_tf32(D1s[(k0 + tg + 4) * S1 + row0]);
        af[3] = to_tf32(D1s[(k0 + tg + 4) * S1 + row0 + 8]);
        uint32_t bf[9][2];
#pragma unroll
        for (int nt = 0; nt < 9; nt++) {
            int sc = nt * 8 + gq;
            bf[nt][0] = to_tf32(D2s[sc * S2 + k0 + tg]);
            bf[nt][1] = to_tf32(D2s[sc * S2 + k0 + tg + 4]);
        }
#pragma unroll
        for (int nt = 0; nt < 9; nt++) mma_tf32(acc[nt], af, bf[nt]);
    }

#pragma unroll
    for (int nt = 0; nt < 9; nt++) {
        const int s0 = nt * 8 + tg * 2;
        if (row0 < 65) {
            if (s0 < 65)     outp[s0 * 66 + row0]       = acc[nt][0];
            if (s0 + 1 < 65) outp[(s0 + 1) * 66 + row0] = acc[nt][1];
        }
        if (row0 + 8 < 65) {
            if (s0 < 65)     outp[s0 * 66 + row0 + 8]       = acc[nt][2];
            if (s0 + 1 < 65) outp[(s0 + 1) * 66 + row0 + 8] = acc[nt][3];
        }
    }
}

// ---------------------------------------------------------------------------
// Kernel 3: warp-specialized scan over OCT tiles (<=16 steps). 224 threads.
// ---------------------------------------------------------------------------
__global__ __launch_bounds__(224) void k_scan(const int* __restrict__ num_frames,
                                              const int* __restrict__ labels,
                                              const int* __restrict__ num_labels,
                                              float* __restrict__ out) {
    extern __shared__ __align__(16) float tilebuf[];   // 4 * SLOT_PAD floats
    __shared__ __align__(16) float beta_sh[2][68];
    __shared__ float maxw[2];
    __shared__ float nm_fin[Un + 1];
    __shared__ int ne_fin[Un + 1];
    __shared__ int esum_sh;
    __shared__ __align__(8) unsigned long long mbars[8];   // full[0..3], empty[4..7]

    const int b = blockIdx.x;
    const int tid = threadIdx.x;
    const int wid = tid >> 5;
    const int lane = tid & 31;
    const int Tb = num_frames[b];          // in [64, 128]
    const int To = (Tb + 7) >> 3;          // oct steps, in [8, 16]

    uint32_t mb_full[4], mb_empty[4];
#pragma unroll
    for (int s = 0; s < 4; s++) {
        mb_full[s] = smem_u32(&mbars[s]);
        mb_empty[s] = smem_u32(&mbars[4 + s]);
    }
    if (tid == 0) {
#pragma unroll
        for (int s = 0; s < 4; s++) {
            MBAR_INIT(mb_full[s], 32);
            MBAR_INIT(mb_empty[s], 2);
        }
    }
    if (tid < 68) {
        beta_sh[0][tid] = (tid == 0) ? 1.f : 0.f;
        beta_sh[1][tid] = 0.f;
    }
    __syncthreads();

    const float* pbase = g_oct + (size_t)(b * 16) * SLOT_PAD;

    if (wid >= 3) {
        const int p = wid - 3;
        const uint32_t dst0 = smem_u32(tilebuf) + p * SLOT_BYTES;
        int eph = 1;
        for (int pp = p; pp < To; pp += 4) {
            mbar_wait(mb_empty[p], (uint32_t)eph);
            eph ^= 1;
            const float* src = pbase + (size_t)pp * SLOT_PAD;
#pragma unroll
            for (int i = lane; i < SLOT_PAD / 4; i += 32)
                cp_async16(dst0 + i * 16, src + i * 4);
            CP_COMMIT();
            CP_WAIT0();
            MBAR_ARRIVE(mb_full[p]);
        }
    } else if (wid < 2) {
        const int st = wid * 32 + lane;
        const bool ex = (wid == 1 && lane == 31);
        const int rowoff = st * CSTRIDE;
        float nv64 = 0.f;
        int esum = 0;

        for (int pp = 0; pp < To; pp++) {
            const int s = pp & 3;
            mbar_wait(mb_full[s], (uint32_t)((pp >> 2) & 1));
            const float* Tt = tilebuf + s * SLOT_PAD;
            const float* bsh = beta_sh[pp & 1];
            const float2* b2 = reinterpret_cast<const float2*>(bsh);

            const float2* r2 = reinterpret_cast<const float2*>(Tt + rowoff);
            float s0 = 0.f, s1 = 0.f, s2 = 0.f, s3 = 0.f;
#pragma unroll 8
            for (int c2 = 0; c2 < 32; c2 += 2) {
                float2 a0 = r2[c2],     w0v = b2[c2];
                float2 a1 = r2[c2 + 1], w1v = b2[c2 + 1];
                s0 += a0.x * w0v.x; s1 += a0.y * w0v.y;
                s2 += a1.x * w1v.x; s3 += a1.y * w1v.y;
            }
            {
                float2 a32 = r2[32], w32 = b2[32];
                s0 += a32.x * w32.x; s1 += a32.y * w32.y;
            }
            float nv = (s0 + s1) + (s2 + s3);

            if (ex) {
                const float2* r64 = reinterpret_cast<const float2*>(Tt + 64 * CSTRIDE);
                float t0 = 0.f, t1 = 0.f;
#pragma unroll 8
                for (int c2 = 0; c2 < 32; c2++) {
                    float2 a0 = r64[c2], w0v = b2[c2];
                    t0 += a0.x * w0v.x; t1 += a0.y * w0v.y;
                }
                float2 a32 = r64[32], w32 = b2[32];
                nv64 = t0 + t1 + a32.x * w32.x + a32.y * w32.y;
            }

            __syncwarp();
            if (lane == 0) MBAR_ARRIVE(mb_empty[s]);

            {
                float mx = ex ? fmaxf(nv, nv64) : nv;
#pragma unroll
                for (int o = 16; o; o >>= 1)
                    mx = fmaxf(mx, __shfl_xor_sync(0xffffffffu, mx, o));
                if (lane == 0) maxw[wid] = mx;
                asm volatile("bar.sync 1, 64;" ::: "memory");
                float gm = fmaxf(maxw[0], maxw[1]);
                int eb = ((__float_as_int(gm) >> 23) & 0xFF) - 127;
                float sc = exp2i(-eb);
                nv *= sc; nv64 *= sc; esum += eb;
            }

            beta_sh[1 - (pp & 1)][st] = nv;
            if (ex) beta_sh[1 - (pp & 1)][64] = nv64;
            asm volatile("bar.sync 1, 64;" ::: "memory");
        }
        if (tid == 0) esum_sh = esum;
    } else {
        // numerator (warp 2): static-indexed 4-deep register ring over g_den
        const float* base = g_den + (size_t)(b * Tn) * TILE_PAD;
        const int* lb = labels + b * Un;
        const int j = lane;
        const int cj = (j == 0) ? 0 : lb[j - 1];
        const int cm = (j >= 2) ? lb[j - 2] : 0;
        const int c32 = lb[31], c31 = lb[30];
        const bool l0 = (j == 0);
        float m = l0 ? 1.f : 0.f;
        int e = l0 ? 0 : EMIN;
        float m2 = 0.f;
        int e2 = EMIN;

        const float* gA = base + cj;
        const float* gB = base + cj * CSTRIDE + cm;
        const float* gC = base + c32;
        const float* gD = base + c32 * CSTRIDE + c31;

        float va[4], vb[4], vc[4], vd[4];
#pragma unroll
        for (int k = 0; k < 4; k++) {
            size_t o = (size_t)k * TILE_PAD;
            va[k] = gA[o];
            vb[k] = (j > 0) ? gB[o] : 0.f;
            vc[k] = l0 ? gC[o] : 0.f;
            vd[k] = l0 ? gD[o] : 0.f;
        }

        for (int tb = 0; tb < Tb; tb += 4) {
            float na[4], nb[4], nc[4], nd[4];
#pragma unroll
            for (int k = 0; k < 4; k++) {
                int tt = tb + 4 + k;
                if (tt > Tb - 1) tt = Tb - 1;
                size_t o = (size_t)tt * TILE_PAD;
                na[k] = gA[o];
                nb[k] = (j > 0) ? gB[o] : 0.f;
                nc[k] = l0 ? gC[o] : 0.f;
                nd[k] = l0 ? gD[o] : 0.f;
            }
#pragma unroll
            for (int k = 0; k < 4; k++) {
                if (tb + k < Tb) {
                    float mp = __shfl_up_sync(0xffffffffu, m, 1);
                    int epv = __shfl_up_sync(0xffffffffu, e, 1);
                    float m31 = __shfl_sync(0xffffffffu, m, 31);
                    int e31 = __shfl_sync(0xffffffffu, e, 31);

                    float own = m * va[k];
                    float oth = (j > 0) ? mp * vb[k] : 0.f;
                    int epo = (j > 0) ? epv : EMIN;
                    accum2(own, e, oth, epo, m, e);

                    if (l0) {
                        float own2 = m2 * vc[k];
                        float oth2 = m31 * vd[k];
                        accum2(own2, e2, oth2, e31, m2, e2);
                    }
                }
            }
#pragma unroll
            for (int k = 0; k < 4; k++) { va[k] = na[k]; vb[k] = nb[k]; vc[k] = nc[k]; vd[k] = nd[k]; }
        }
        nm_fin[j] = m;
        ne_fin[j] = e;
        if (l0) { nm_fin[32] = m2; ne_fin[32] = e2; }
    }

    __syncthreads();
    if (tid == 0) {
        const float* bf = beta_sh[To & 1];
        float ssum = 0.f;
        for (int c = 0; c < Cn; c++) ssum += bf[c];
        float den = (float)esum_sh * LN2F + __logf(ssum);
        int nl = num_labels[b];
        float num = __logf(nm_fin[nl]) + (float)ne_fin[nl] * LN2F;
        out[b] = den - num;
    }
}

// ---------------------------------------------------------------------------
extern "C" void kernel_launch(void* const* d_in, const int* in_sizes, int n_in,
                              void* d_out, int out_size) {
    const float* frames = (const float*)d_in[0];   // (8,128,512)
    const float* Wf     = (const float*)d_in[1];   // (512,512)
    const float* ce     = (const float*)d_in[2];   // (65,512)
    const float* Wo     = (const float*)d_in[3];   // (512,65)
    const int* nf       = (const int*)d_in[4];     // (8,)
    const int* labels   = (const int*)d_in[5];     // (8,32)
    const int* nl       = (const int*)d_in[6];     // (8,)
    float* out = (float*)d_out;                    // (8,)

    cudaFuncSetAttribute(k_logits, cudaFuncAttributeMaxDynamicSharedMemorySize, DYN_SMEM);
    cudaFuncSetAttribute(k_scan, cudaFuncAttributeMaxDynamicSharedMemorySize, SCAN_SMEM);

    k_prep<<<4, 256>>>(Wo);
    k_proj<<<dim3(Hn / 32, (Bn * Tn) / 64), 128>>>(frames, Wf);
    k_logits<<<NB_LOGITS, 256, DYN_SMEM>>>(ce);
    k_pair<<<dim3(64, Bn), 160>>>(nf);
    k_mul<<<dim3(32, Bn), 160>>>(nf, 1);
    k_mul<<<dim3(16, Bn), 160>>>(nf, 2);
    k_scan<<<Bn, 224, SCAN_SMEM>>>(nf, labels, nl, out);
}